// round 1
// baseline (speedup 1.0000x reference)
#include <cuda_runtime.h>
#include <cuda_bf16.h>

#define SEM_DIMV 512
#define SEM_SIZEV 2048
#define ACO_DIMV 32
#define BB 16
#define TT 4096
#define DTOT 544
#define NROWS (BB*TT)
#define HALFV 4.0f
#define EPSV 1e-5f

// scratch (allocation-free rule: __device__ globals)
__device__ float g_emb[SEM_SIZEV * SEM_DIMV];   // row-major [code][d]
__device__ float g_embT[SEM_DIMV * SEM_SIZEV];  // transposed [d][code]
__device__ float g_esq[SEM_SIZEV];              // |e|^2 per code

// ---------------------------------------------------------------------------
// Kernel 1: normalize embeddings, build transpose, per-code squared norms
// ---------------------------------------------------------------------------
__global__ void prep_kernel(const float* __restrict__ esum,
                            const float* __restrict__ usage) {
    int c = blockIdx.x;          // 2048 blocks
    int tid = threadIdx.x;       // 128 threads
    float inv = 1.0f / fmaxf(usage[c], EPSV);
    float acc = 0.0f;
#pragma unroll
    for (int i = 0; i < 4; i++) {
        int d = tid + i * 128;
        float e = esum[c * SEM_DIMV + d] * inv;
        g_emb[c * SEM_DIMV + d] = e;
        g_embT[d * SEM_SIZEV + c] = e;
        acc += e * e;
    }
    __shared__ float red[128];
    red[tid] = acc;
    __syncthreads();
    if (tid < 64) red[tid] += red[tid + 64];
    __syncthreads();
    if (tid < 32) {
        float v = red[tid] + red[tid + 32];
#pragma unroll
        for (int o = 16; o > 0; o >>= 1) v += __shfl_down_sync(0xffffffffu, v, o);
        if (tid == 0) g_esq[c] = v;
    }
}

// ---------------------------------------------------------------------------
// Kernel 2: fused distance-GEMM + argmin + sem epilogue (codes + quantized)
//   block = 256 threads, handles 128 rows (one b, 128 consecutive t)
// ---------------------------------------------------------------------------
__global__ __launch_bounds__(256)
void sem_kernel(const float* __restrict__ x,
                const float* __restrict__ probs_sem,
                float* __restrict__ outq,
                float* __restrict__ outc) {
    __shared__ __align__(16) float smbuf[2 * 32 * 132];  // xs | es, reused later
    __shared__ int codes_s[128];

    int tid = threadIdx.x;
    int tx = tid & 15;          // code group
    int ty = tid >> 4;          // row group
    int row0 = blockIdx.x * 128;
    int b  = row0 >> 12;        // / 4096
    int t0 = row0 & 4095;

    const float* xb = x + (size_t)b * DTOT * TT + t0;

    float bestv[8];
    int   besti[8];
#pragma unroll
    for (int i = 0; i < 8; i++) { bestv[i] = 3.4e38f; besti[i] = 0; }

    for (int cc = 0; cc < SEM_SIZEV; cc += 128) {
        float acc[8][8];
#pragma unroll
        for (int i = 0; i < 8; i++)
#pragma unroll
            for (int j = 0; j < 8; j++) acc[i][j] = 0.0f;

        for (int kk = 0; kk < SEM_DIMV; kk += 32) {
            __syncthreads();
            // load 32x128 x-tile and 32x128 embT-tile (float4, coalesced)
#pragma unroll
            for (int l = 0; l < 4; l++) {
                int idx = tid + l * 256;            // 0..1023
                int k  = idx >> 5;                  // 0..31
                int r4 = (idx & 31) << 2;           // 0,4,...,124
                float4 vx = *(const float4*)(xb + (size_t)(kk + k) * TT + r4);
                *(float4*)&smbuf[k * 132 + r4] = vx;
                float4 ve = *(const float4*)(g_embT + (size_t)(kk + k) * SEM_SIZEV + cc + r4);
                *(float4*)&smbuf[32 * 132 + k * 132 + r4] = ve;
            }
            __syncthreads();
#pragma unroll
            for (int k = 0; k < 32; k++) {
                float4 a0 = *(float4*)&smbuf[k * 132 + ty * 8];
                float4 a1 = *(float4*)&smbuf[k * 132 + ty * 8 + 4];
                float4 b0 = *(float4*)&smbuf[32 * 132 + k * 132 + tx * 8];
                float4 b1 = *(float4*)&smbuf[32 * 132 + k * 132 + tx * 8 + 4];
                float av[8] = {a0.x, a0.y, a0.z, a0.w, a1.x, a1.y, a1.z, a1.w};
                float bv2[8] = {b0.x, b0.y, b0.z, b0.w, b1.x, b1.y, b1.z, b1.w};
#pragma unroll
                for (int i = 0; i < 8; i++)
#pragma unroll
                    for (int j = 0; j < 8; j++)
                        acc[i][j] += av[i] * bv2[j];
            }
        }
        // scores & running argmin (ascending code order -> first-index ties)
#pragma unroll
        for (int j = 0; j < 8; j++) {
            int c = cc + tx * 8 + j;
            float eq = g_esq[c];
#pragma unroll
            for (int i = 0; i < 8; i++) {
                float s = eq - 2.0f * acc[i][j];
                if (s < bestv[i]) { bestv[i] = s; besti[i] = c; }
            }
        }
    }

    // cross-thread (tx) reduction via smem (reuse smbuf)
    __syncthreads();
    float* bv = smbuf;                       // [128][17]
    int*   bi = (int*)(smbuf + 128 * 17);    // [128][17]
#pragma unroll
    for (int i = 0; i < 8; i++) {
        bv[(ty * 8 + i) * 17 + tx] = bestv[i];
        bi[(ty * 8 + i) * 17 + tx] = besti[i];
    }
    __syncthreads();
    if (tid < 128) {
        float best = bv[tid * 17];
        int   bst  = bi[tid * 17];
#pragma unroll
        for (int s = 1; s < 16; s++) {
            float v = bv[tid * 17 + s];
            int   c = bi[tid * 17 + s];
            if (v < best || (v == best && c < bst)) { best = v; bst = c; }
        }
        codes_s[tid] = bst;
        outc[(size_t)b * 33 * TT + t0 + tid] = (float)bst;
    }
    __syncthreads();

    float psem = probs_sem[b];               // uniform across block
    float* outqb = outq + (size_t)b * DTOT * TT + t0;

    if (psem < 0.5f) {
        // gather emb[code[r]] with smem transpose, chunks of 32 dims
        int r = tid >> 1, half = tid & 1;
        const float* erow = g_emb + (size_t)codes_s[r] * SEM_DIMV;
        for (int dc = 0; dc < SEM_DIMV; dc += 32) {
            __syncthreads();
#pragma unroll
            for (int q = 0; q < 4; q++) {
                int dd = half * 16 + q * 4;
                float4 v = *(const float4*)(erow + dc + dd);
                smbuf[(dd + 0) * 132 + r] = v.x;
                smbuf[(dd + 1) * 132 + r] = v.y;
                smbuf[(dd + 2) * 132 + r] = v.z;
                smbuf[(dd + 3) * 132 + r] = v.w;
            }
            __syncthreads();
#pragma unroll
            for (int it = 0; it < 4; it++) {
                int idx = it * 256 + tid;        // 1024 float4
                int k  = idx >> 5;
                int r4 = (idx & 31) << 2;
                *(float4*)(outqb + (size_t)(dc + k) * TT + r4) =
                    *(float4*)&smbuf[k * 132 + r4];
            }
        }
    } else {
        // straight copy of x (coalesced float4 both sides)
        for (int it = 0; it < 64; it++) {
            int idx = it * 256 + tid;            // 16384 float4 = 512x128 floats
            int k  = idx >> 5;
            int r4 = (idx & 31) << 2;
            *(float4*)(outqb + (size_t)k * TT + r4) =
                *(const float4*)(xb + (size_t)k * TT + r4);
        }
    }
}

// ---------------------------------------------------------------------------
// Kernel 3: ACO quantizer (elementwise)
// ---------------------------------------------------------------------------
__global__ void aco_kernel(const float* __restrict__ x,
                           const float* __restrict__ noise,
                           const float* __restrict__ probs_aco,
                           float* __restrict__ outq,
                           float* __restrict__ outc) {
    int idx = blockIdx.x * blockDim.x + threadIdx.x;   // 0..2097151
    int t  = idx & 4095;
    int rj = idx >> 12;        // b*32 + j
    int b  = rj >> 5;
    int j  = rj & 31;

    float a  = x[((size_t)b * DTOT + SEM_DIMV + j) * TT + t];
    float zb = tanhf(a) * HALFV;
    float pa = probs_aco[b];
    float zout;
    if (pa < 0.5f) {
        zout = rintf(zb);                      // z_q == round(z_b) numerically
    } else if (pa < 0.75f) {
        float ns = (noise[(size_t)rj * TT + t] * 2.0f - 1.0f) * (HALFV / 9.0f);
        zout = fminf(fmaxf(zb + ns, -HALFV), HALFV);
    } else {
        zout = zb;
    }
    float code = fminf(fmaxf(rintf(zout + HALFV), 0.0f), 8.0f);
    outq[((size_t)b * DTOT + SEM_DIMV + j) * TT + t] = zout * 0.25f;
    outc[((size_t)b * 33 + 1 + j) * TT + t] = code;
}

// ---------------------------------------------------------------------------
extern "C" void kernel_launch(void* const* d_in, const int* in_sizes, int n_in,
                              void* d_out, int out_size) {
    const float* x     = (const float*)d_in[0];
    const float* esum  = (const float*)d_in[1];
    const float* usage = (const float*)d_in[2];
    const float* noise = (const float*)d_in[3];
    const float* psem  = (const float*)d_in[4];
    const float* paco  = (const float*)d_in[5];

    float* outq = (float*)d_out;                         // (16,544,4096)
    float* outc = outq + (size_t)BB * DTOT * TT;         // (16,33,4096) as float

    prep_kernel<<<SEM_SIZEV, 128>>>(esum, usage);
    sem_kernel<<<NROWS / 128, 256>>>(x, psem, outq, outc);
    aco_kernel<<<(BB * ACO_DIMV * TT) / 256, 256>>>(x, noise, paco, outq, outc);
}

// round 3
// speedup vs baseline: 3.4250x; 3.4250x over previous
#include <cuda_runtime.h>
#include <cuda_bf16.h>
#include <cstdint>

#define SEM_DIMV 512
#define SEM_SIZEV 2048
#define ACO_DIMV 32
#define BB 16
#define TT 4096
#define NROWS (BB*TT)
#define DTOT 544
#define HALFV 4.0f
#define EPSV 1e-5f

#define NC_COUNT 8       // 8 chunks of 256 codes
#define KK_COUNT 8       // 8 chunks of 64 k
#define SLOT_BYTES 98304 // A 32KB (hi+lo) + B 64KB (hi+lo)
#define ESQ_OFF (2*SLOT_BYTES)
#define DYN_BYTES (ESQ_OFF + 8192 + 1024)

// A: per (tile,kk): hi[128m][64k] bf16 swizzled (16KB) + lo (16KB)
// B: per (nc,kk):  hi[256c][64k] bf16 swizzled (32KB) + lo (32KB)
__device__ __align__(128) unsigned char g_A[512 * 8 * 32768];  // 128MB
__device__ __align__(128) unsigned char g_B[64 * 65536];       // 4MB
__device__ float g_emb[SEM_SIZEV * SEM_DIMV];
__device__ float g_esq[SEM_SIZEV];

// ------------------------------------------------------------------ helpers
__device__ __forceinline__ uint32_t smem_u32(const void* p) {
    uint32_t a;
    asm("{ .reg .u64 t; cvta.to.shared.u64 t, %1; cvt.u32.u64 %0, t; }" : "=r"(a) : "l"(p));
    return a;
}
__device__ __forceinline__ void mbar_init(uint32_t a, uint32_t cnt) {
    asm volatile("mbarrier.init.shared.b64 [%0], %1;" :: "r"(a), "r"(cnt) : "memory");
}
__device__ __forceinline__ void mbar_expect_tx(uint32_t a, uint32_t bytes) {
    asm volatile("mbarrier.arrive.expect_tx.shared.b64 _, [%0], %1;" :: "r"(a), "r"(bytes) : "memory");
}
__device__ __forceinline__ void mbar_wait(uint32_t a, uint32_t parity) {
    asm volatile(
        "{\n\t.reg .pred P;\n\t"
        "W_%=:\n\t"
        "mbarrier.try_wait.parity.acquire.cta.shared::cta.b64 P, [%0], %1, 0x989680;\n\t"
        "@!P bra W_%=;\n\t}"
        :: "r"(a), "r"(parity) : "memory");
}
__device__ __forceinline__ void bulk_g2s(uint32_t dst, const void* src, uint32_t bytes, uint32_t mbar) {
    asm volatile("cp.async.bulk.shared::cluster.global.mbarrier::complete_tx::bytes [%0], [%1], %2, [%3];"
        :: "r"(dst), "l"(src), "r"(bytes), "r"(mbar) : "memory");
}

#define LDSM4(R0,R1,R2,R3,ADDR) \
    asm volatile("ldmatrix.sync.aligned.m8n8.x4.shared.b16 {%0,%1,%2,%3}, [%4];" \
        : "=r"(R0), "=r"(R1), "=r"(R2), "=r"(R3) : "r"(ADDR))

#define MMA16816(D, A0,A1,A2,A3, B0,B1) \
    asm volatile("mma.sync.aligned.m16n8k16.row.col.f32.bf16.bf16.f32 " \
        "{%0,%1,%2,%3},{%4,%5,%6,%7},{%8,%9},{%0,%1,%2,%3};" \
        : "+f"((D)[0]), "+f"((D)[1]), "+f"((D)[2]), "+f"((D)[3]) \
        : "r"(A0), "r"(A1), "r"(A2), "r"(A3), "r"(B0), "r"(B1))

__device__ __forceinline__ void split_pack(float f0, float f1, uint32_t& hp, uint32_t& lp) {
    __nv_bfloat16 h0 = __float2bfloat16(f0);
    __nv_bfloat16 h1 = __float2bfloat16(f1);
    __nv_bfloat16 l0 = __float2bfloat16(f0 - __bfloat162float(h0));
    __nv_bfloat16 l1 = __float2bfloat16(f1 - __bfloat162float(h1));
    hp = (uint32_t)__bfloat16_as_ushort(h0) | ((uint32_t)__bfloat16_as_ushort(h1) << 16);
    lp = (uint32_t)__bfloat16_as_ushort(l0) | ((uint32_t)__bfloat16_as_ushort(l1) << 16);
}

// ---------------------------------------------------------------------------
// prep_emb: emb fp32 + |e|^2
// ---------------------------------------------------------------------------
__global__ void prep_emb_kernel(const float* __restrict__ esum,
                                const float* __restrict__ usage) {
    int c = blockIdx.x, tid = threadIdx.x;
    float inv = 1.0f / fmaxf(usage[c], EPSV);
    float acc = 0.0f;
#pragma unroll
    for (int i = 0; i < 4; i++) {
        int d = tid + i * 128;
        float e = esum[c * SEM_DIMV + d] * inv;
        g_emb[c * SEM_DIMV + d] = e;
        acc += e * e;
    }
    __shared__ float red[128];
    red[tid] = acc;
    __syncthreads();
    if (tid < 64) red[tid] += red[tid + 64];
    __syncthreads();
    if (tid < 32) {
        float v = red[tid] + red[tid + 32];
#pragma unroll
        for (int o = 16; o > 0; o >>= 1) v += __shfl_down_sync(0xffffffffu, v, o);
        if (tid == 0) g_esq[c] = v;
    }
}

// ---------------------------------------------------------------------------
// prep_B: codebook -> bf16 hi/lo swizzled tiles [c][k], chunk^ (row&7)
// ---------------------------------------------------------------------------
__global__ void prep_B_kernel() {
    int tb = blockIdx.x;                 // nc*8 + kk
    int nc = tb >> 3, kk = tb & 7;
    size_t base = (size_t)tb * 65536;
    for (int q = threadIdx.x; q < 2048; q += 256) {
        int m = q >> 3, c = q & 7;       // code row (0..255), k-chunk (0..7)
        const float* row = g_emb + (size_t)(nc * 256 + m) * SEM_DIMV + kk * 64 + c * 8;
        uint32_t hp[4], lp[4];
#pragma unroll
        for (int i = 0; i < 4; i++) split_pack(row[2*i], row[2*i+1], hp[i], lp[i]);
        uint32_t off = (uint32_t)m * 128 + ((uint32_t)(c ^ (m & 7)) << 4);
        *(uint4*)(g_B + base + off)         = make_uint4(hp[0], hp[1], hp[2], hp[3]);
        *(uint4*)(g_B + base + 32768 + off) = make_uint4(lp[0], lp[1], lp[2], lp[3]);
    }
}

// ---------------------------------------------------------------------------
// prep_A: x sem rows -> bf16 hi/lo swizzled tiles [m][k]
// ---------------------------------------------------------------------------
__global__ __launch_bounds__(256)
void prep_A_kernel(const float* __restrict__ x) {
    __shared__ float s[64 * 129];
    int tile = blockIdx.x >> 3, kk = blockIdx.x & 7;
    int b = tile >> 5, t0 = (tile & 31) * 128;
    int tid = threadIdx.x;
#pragma unroll
    for (int i = 0; i < 32; i++) {
        int idx = i * 256 + tid;
        int k = idx >> 7, m = idx & 127;
        s[k * 129 + m] = x[((size_t)(b * DTOT + kk * 64 + k)) * TT + t0 + m];
    }
    __syncthreads();
    size_t base = (size_t)blockIdx.x * 32768;
    for (int q = tid; q < 1024; q += 256) {
        int m = q >> 3, c = q & 7;
        uint32_t hp[4], lp[4];
#pragma unroll
        for (int i = 0; i < 4; i++)
            split_pack(s[(c * 8 + 2*i) * 129 + m], s[(c * 8 + 2*i + 1) * 129 + m], hp[i], lp[i]);
        uint32_t off = (uint32_t)m * 128 + ((uint32_t)(c ^ (m & 7)) << 4);
        *(uint4*)(g_A + base + off)         = make_uint4(hp[0], hp[1], hp[2], hp[3]);
        *(uint4*)(g_A + base + 16384 + off) = make_uint4(lp[0], lp[1], lp[2], lp[3]);
    }
}

// ---------------------------------------------------------------------------
// sem_mma: bf16 3-pass mma.sync distance GEMM + argmin + epilogue
// ---------------------------------------------------------------------------
__global__ __launch_bounds__(256, 1)
void sem_mma_kernel(const float* __restrict__ x,
                    const float* __restrict__ probs_sem,
                    float* __restrict__ outq,
                    float* __restrict__ outc) {
    extern __shared__ unsigned char dynraw[];
    __shared__ __align__(8) unsigned long long bars[2];
    __shared__ int codes_s[128];

    uint32_t raw = smem_u32(dynraw);
    uint32_t abase = (raw + 1023u) & ~1023u;
    float* esq_s = (float*)(dynraw + (abase - raw) + ESQ_OFF);
    float* smbuf = (float*)(dynraw + (abase - raw));
    uint32_t barf[2] = { smem_u32(&bars[0]), smem_u32(&bars[1]) };

    int tid = threadIdx.x;
    int lane = tid & 31;
    int wid = tid >> 5;
    int warpM = wid >> 2, warpN = wid & 3;

    int tile = blockIdx.x;
    int b = tile >> 5, t0 = (tile & 31) * 128;

    if (tid == 0) { mbar_init(barf[0], 1); mbar_init(barf[1], 1); }
    for (int i = tid; i < SEM_SIZEV; i += 256) esq_s[i] = g_esq[i];
    __syncthreads();

    const unsigned char* srcA = g_A + (size_t)tile * (8 * 32768);

    if (tid == 0) {
#pragma unroll
        for (int s = 0; s < 2; s++) {      // prologue: slots 0,1 = (nc0,kk0),(nc0,kk1)
            mbar_expect_tx(barf[s], SLOT_BYTES);
            bulk_g2s(abase + s * SLOT_BYTES, srcA + (size_t)(s & 7) * 32768, 32768, barf[s]);
            bulk_g2s(abase + s * SLOT_BYTES + 32768, g_B + (size_t)s * 65536, 65536, barf[s]);
        }
    }

    // per-thread ldmatrix geometry
    uint32_t sw = lane & 7;
    uint32_t aRowOff = (uint32_t)(warpM * 64 + (lane & 15)) * 128;
    uint32_t aAdd = lane >> 4;                         // 0/1 : k-half
    uint32_t bRowOff = (uint32_t)(warpN * 64 + (lane & 7) + ((lane & 16) >> 1)) * 128;
    uint32_t bAdd = (lane >> 3) & 1;

    float acc[4][8][4];
    float bestv[4][2];
    int   besti[4][2];
#pragma unroll
    for (int mi = 0; mi < 4; mi++)
#pragma unroll
        for (int h = 0; h < 2; h++) { bestv[mi][h] = 3.4e38f; besti[mi][h] = 0; }

    for (int s = 0; s < NC_COUNT * KK_COUNT; s++) {
        int kk = s & 7, slot = s & 1;
        mbar_wait(barf[slot], (s >> 1) & 1);
        uint32_t sb = abase + slot * SLOT_BYTES;

        if (kk == 0) {
#pragma unroll
            for (int mi = 0; mi < 4; mi++)
#pragma unroll
                for (int nf = 0; nf < 8; nf++)
#pragma unroll
                    for (int e = 0; e < 4; e++) acc[mi][nf][e] = 0.0f;
        }

#pragma unroll 1
        for (int pass = 0; pass < 3; pass++) {
            uint32_t aoff = sb + ((pass == 2) ? 16384u : 0u);
            uint32_t boff = sb + 32768u + ((pass == 1) ? 32768u : 0u);
#pragma unroll
            for (int j = 0; j < 4; j++) {
                uint32_t ar[4][4], br[4][4];
                uint32_t ca = (uint32_t)(((2 * j + aAdd) ^ sw) << 4);
                uint32_t cb = (uint32_t)(((2 * j + bAdd) ^ sw) << 4);
#pragma unroll
                for (int mi = 0; mi < 4; mi++)
                    LDSM4(ar[mi][0], ar[mi][1], ar[mi][2], ar[mi][3],
                          aoff + aRowOff + mi * 2048 + ca);
#pragma unroll
                for (int nf2 = 0; nf2 < 4; nf2++)
                    LDSM4(br[nf2][0], br[nf2][1], br[nf2][2], br[nf2][3],
                          boff + bRowOff + nf2 * 2048 + cb);
#pragma unroll
                for (int mi = 0; mi < 4; mi++)
#pragma unroll
                    for (int nf2 = 0; nf2 < 4; nf2++) {
                        MMA16816(acc[mi][2 * nf2],     ar[mi][0], ar[mi][1], ar[mi][2], ar[mi][3],
                                 br[nf2][0], br[nf2][1]);
                        MMA16816(acc[mi][2 * nf2 + 1], ar[mi][0], ar[mi][1], ar[mi][2], ar[mi][3],
                                 br[nf2][2], br[nf2][3]);
                    }
            }
        }
        __syncthreads();                   // slot free
        if (tid == 0 && s + 2 < NC_COUNT * KK_COUNT) {
            int s2 = s + 2, nc2 = s2 >> 3, kk2 = s2 & 7;
            mbar_expect_tx(barf[slot], SLOT_BYTES);
            bulk_g2s(sb, srcA + (size_t)kk2 * 32768, 32768, barf[slot]);
            bulk_g2s(sb + 32768, g_B + (size_t)(nc2 * 8 + kk2) * 65536, 65536, barf[slot]);
        }

        if (kk == 7) {                     // score this 256-code chunk
            int nc = s >> 3;
            int cbase = nc * 256 + warpN * 64 + (lane & 3) * 2;
#pragma unroll
            for (int nf = 0; nf < 8; nf++) {
                float eq0 = esq_s[cbase + nf * 8 + 0];
                float eq1 = esq_s[cbase + nf * 8 + 1];
#pragma unroll
                for (int mi = 0; mi < 4; mi++) {
                    float s00 = eq0 - 2.0f * acc[mi][nf][0];
                    float s01 = eq1 - 2.0f * acc[mi][nf][1];
                    float s10 = eq0 - 2.0f * acc[mi][nf][2];
                    float s11 = eq1 - 2.0f * acc[mi][nf][3];
                    int c0 = cbase + nf * 8, c1 = c0 + 1;
                    if (s00 < bestv[mi][0]) { bestv[mi][0] = s00; besti[mi][0] = c0; }
                    if (s01 < bestv[mi][0]) { bestv[mi][0] = s01; besti[mi][0] = c1; }
                    if (s10 < bestv[mi][1]) { bestv[mi][1] = s10; besti[mi][1] = c0; }
                    if (s11 < bestv[mi][1]) { bestv[mi][1] = s11; besti[mi][1] = c1; }
                }
            }
        }
    }

    // cross-lane reduce (lanes sharing a row differ only in lane&3)
    __syncthreads();                       // esq_s reads done -> reuse as reduction buf
    float* redV = esq_s;                   // [128][4]
    int*   redI = (int*)(esq_s + 512);     // [128][4]
#pragma unroll
    for (int mi = 0; mi < 4; mi++)
#pragma unroll
        for (int h = 0; h < 2; h++) {
            float v = bestv[mi][h];
            int   i = besti[mi][h];
#pragma unroll
            for (int off = 1; off <= 2; off <<= 1) {
                float ov = __shfl_xor_sync(0xffffffffu, v, off);
                int   oi = __shfl_xor_sync(0xffffffffu, i, off);
                if (ov < v || (ov == v && oi < i)) { v = ov; i = oi; }
            }
            if ((lane & 3) == 0) {
                int row = warpM * 64 + mi * 16 + (lane >> 2) + h * 8;
                redV[row * 4 + warpN] = v;
                redI[row * 4 + warpN] = i;
            }
        }
    __syncthreads();
    if (tid < 128) {
        float best = redV[tid * 4];
        int   bst  = redI[tid * 4];
#pragma unroll
        for (int w = 1; w < 4; w++) {
            float v = redV[tid * 4 + w];
            int   i = redI[tid * 4 + w];
            if (v < best || (v == best && i < bst)) { best = v; bst = i; }
        }
        codes_s[tid] = bst;
        outc[(size_t)b * 33 * TT + t0 + tid] = (float)bst;
    }
    __syncthreads();

    // ---------------- output phase ----------------
    float psem = probs_sem[b];
    const float* xb = x + (size_t)b * DTOT * TT + t0;
    float* outqb = outq + (size_t)b * DTOT * TT + t0;

    if (psem < 0.5f) {
        int r = tid >> 1, half = tid & 1;
        const float* erow = g_emb + (size_t)codes_s[r] * SEM_DIMV;
        for (int dc = 0; dc < SEM_DIMV; dc += 32) {
            __syncthreads();
#pragma unroll
            for (int q = 0; q < 4; q++) {
                int dd = half * 16 + q * 4;
                float4 v = *(const float4*)(erow + dc + dd);
                smbuf[(dd + 0) * 132 + r] = v.x;
                smbuf[(dd + 1) * 132 + r] = v.y;
                smbuf[(dd + 2) * 132 + r] = v.z;
                smbuf[(dd + 3) * 132 + r] = v.w;
            }
            __syncthreads();
#pragma unroll
            for (int it = 0; it < 4; it++) {
                int idx = it * 256 + tid;
                int k = idx >> 5, r4 = (idx & 31) << 2;
                *(float4*)(outqb + (size_t)(dc + k) * TT + r4) = *(float4*)&smbuf[k * 132 + r4];
            }
        }
    } else {
        for (int it = 0; it < 64; it++) {
            int idx = it * 256 + tid;
            int k = idx >> 5, r4 = (idx & 31) << 2;
            *(float4*)(outqb + (size_t)k * TT + r4) = *(const float4*)(xb + (size_t)k * TT + r4);
        }
    }
}

// ---------------------------------------------------------------------------
// aco: elementwise quantizer
// ---------------------------------------------------------------------------
__global__ void aco_kernel(const float* __restrict__ x,
                           const float* __restrict__ noise,
                           const float* __restrict__ probs_aco,
                           float* __restrict__ outq,
                           float* __restrict__ outc) {
    int idx = blockIdx.x * blockDim.x + threadIdx.x;
    int t = idx & 4095;
    int rj = idx >> 12;
    int b = rj >> 5, j = rj & 31;

    float a = x[((size_t)b * DTOT + SEM_DIMV + j) * TT + t];
    float zb = tanhf(a) * HALFV;
    float pa = probs_aco[b];
    float zout;
    if (pa < 0.5f) {
        zout = rintf(zb);
    } else if (pa < 0.75f) {
        float ns = (noise[(size_t)rj * TT + t] * 2.0f - 1.0f) * (HALFV / 9.0f);
        zout = fminf(fmaxf(zb + ns, -HALFV), HALFV);
    } else {
        zout = zb;
    }
    float code = fminf(fmaxf(rintf(zout + HALFV), 0.0f), 8.0f);
    outq[((size_t)b * DTOT + SEM_DIMV + j) * TT + t] = zout * 0.25f;
    outc[((size_t)b * 33 + 1 + j) * TT + t] = code;
}

// ---------------------------------------------------------------------------
extern "C" void kernel_launch(void* const* d_in, const int* in_sizes, int n_in,
                              void* d_out, int out_size) {
    const float* x     = (const float*)d_in[0];
    const float* esum  = (const float*)d_in[1];
    const float* usage = (const float*)d_in[2];
    const float* noise = (const float*)d_in[3];
    const float* psem  = (const float*)d_in[4];
    const float* paco  = (const float*)d_in[5];

    float* outq = (float*)d_out;
    float* outc = outq + (size_t)BB * DTOT * TT;

    cudaFuncSetAttribute(sem_mma_kernel,
                         cudaFuncAttributeMaxDynamicSharedMemorySize, DYN_BYTES);

    prep_emb_kernel<<<SEM_SIZEV, 128>>>(esum, usage);
    prep_B_kernel<<<64, 256>>>();
    prep_A_kernel<<<4096, 256>>>(x);
    sem_mma_kernel<<<NROWS / 128, 256, DYN_BYTES>>>(x, psem, outq, outc);
    aco_kernel<<<(BB * ACO_DIMV * TT) / 256, 256>>>(x, noise, paco, outq, outc);
}

// round 4
// speedup vs baseline: 3.7384x; 1.0915x over previous
#include <cuda_runtime.h>
#include <cuda_bf16.h>
#include <cstdint>

#define SEM_DIMV 512
#define SEM_SIZEV 2048
#define ACO_DIMV 32
#define BB 16
#define TT 4096
#define NROWS (BB*TT)
#define DTOT 544
#define HALFV 4.0f
#define EPSV 1e-5f

#define TILE_M 64
#define N_TILES (NROWS/TILE_M)   // 1024
#define NC_COUNT 8               // 8 chunks of 256 codes
#define KK_COUNT 8               // 8 chunks of 64 k
// slot: A hi+lo 16KB @0, B hi+lo 64KB @16384
#define SLOT_BYTES 81920
#define ESQ_OFF (2*SLOT_BYTES)
#define DYN_BYTES (ESQ_OFF + 8192 + 1024)

// A: per (tile,kk): hi[64m][64k] bf16 swizzled (8KB) + lo (8KB) = 16KB
// B: per (nc,kk):  hi[256c][64k] bf16 swizzled (32KB) + lo (32KB) = 64KB
__device__ __align__(128) unsigned char g_A[N_TILES * 8 * 16384];  // 128MB
__device__ __align__(128) unsigned char g_B[64 * 65536];           // 4MB
__device__ float g_emb[SEM_SIZEV * SEM_DIMV];
__device__ float g_esq[SEM_SIZEV];

// ------------------------------------------------------------------ helpers
__device__ __forceinline__ uint32_t smem_u32(const void* p) {
    uint32_t a;
    asm("{ .reg .u64 t; cvta.to.shared.u64 t, %1; cvt.u32.u64 %0, t; }" : "=r"(a) : "l"(p));
    return a;
}
__device__ __forceinline__ void mbar_init(uint32_t a, uint32_t cnt) {
    asm volatile("mbarrier.init.shared.b64 [%0], %1;" :: "r"(a), "r"(cnt) : "memory");
}
__device__ __forceinline__ void mbar_expect_tx(uint32_t a, uint32_t bytes) {
    asm volatile("mbarrier.arrive.expect_tx.shared.b64 _, [%0], %1;" :: "r"(a), "r"(bytes) : "memory");
}
__device__ __forceinline__ void mbar_arrive(uint32_t a) {
    asm volatile("mbarrier.arrive.shared.b64 _, [%0];" :: "r"(a) : "memory");
}
__device__ __forceinline__ void mbar_wait(uint32_t a, uint32_t parity) {
    asm volatile(
        "{\n\t.reg .pred P;\n\t"
        "W_%=:\n\t"
        "mbarrier.try_wait.parity.acquire.cta.shared::cta.b64 P, [%0], %1, 0x989680;\n\t"
        "@!P bra W_%=;\n\t}"
        :: "r"(a), "r"(parity) : "memory");
}
__device__ __forceinline__ void bulk_g2s(uint32_t dst, const void* src, uint32_t bytes, uint32_t mbar) {
    asm volatile("cp.async.bulk.shared::cluster.global.mbarrier::complete_tx::bytes [%0], [%1], %2, [%3];"
        :: "r"(dst), "l"(src), "r"(bytes), "r"(mbar) : "memory");
}

#define LDSM4(R0,R1,R2,R3,ADDR) \
    asm volatile("ldmatrix.sync.aligned.m8n8.x4.shared.b16 {%0,%1,%2,%3}, [%4];" \
        : "=r"(R0), "=r"(R1), "=r"(R2), "=r"(R3) : "r"(ADDR))

#define MMA16816(D, A0,A1,A2,A3, B0,B1) \
    asm volatile("mma.sync.aligned.m16n8k16.row.col.f32.bf16.bf16.f32 " \
        "{%0,%1,%2,%3},{%4,%5,%6,%7},{%8,%9},{%0,%1,%2,%3};" \
        : "+f"((D)[0]), "+f"((D)[1]), "+f"((D)[2]), "+f"((D)[3]) \
        : "r"(A0), "r"(A1), "r"(A2), "r"(A3), "r"(B0), "r"(B1))

__device__ __forceinline__ void split_pack(float f0, float f1, uint32_t& hp, uint32_t& lp) {
    __nv_bfloat16 h0 = __float2bfloat16(f0);
    __nv_bfloat16 h1 = __float2bfloat16(f1);
    __nv_bfloat16 l0 = __float2bfloat16(f0 - __bfloat162float(h0));
    __nv_bfloat16 l1 = __float2bfloat16(f1 - __bfloat162float(h1));
    hp = (uint32_t)__bfloat16_as_ushort(h0) | ((uint32_t)__bfloat16_as_ushort(h1) << 16);
    lp = (uint32_t)__bfloat16_as_ushort(l0) | ((uint32_t)__bfloat16_as_ushort(l1) << 16);
}

// ---------------------------------------------------------------------------
__global__ void prep_emb_kernel(const float* __restrict__ esum,
                                const float* __restrict__ usage) {
    int c = blockIdx.x, tid = threadIdx.x;
    float inv = 1.0f / fmaxf(usage[c], EPSV);
    float acc = 0.0f;
#pragma unroll
    for (int i = 0; i < 4; i++) {
        int d = tid + i * 128;
        float e = esum[c * SEM_DIMV + d] * inv;
        g_emb[c * SEM_DIMV + d] = e;
        acc += e * e;
    }
    __shared__ float red[128];
    red[tid] = acc;
    __syncthreads();
    if (tid < 64) red[tid] += red[tid + 64];
    __syncthreads();
    if (tid < 32) {
        float v = red[tid] + red[tid + 32];
#pragma unroll
        for (int o = 16; o > 0; o >>= 1) v += __shfl_down_sync(0xffffffffu, v, o);
        if (tid == 0) g_esq[c] = v;
    }
}

// ---------------------------------------------------------------------------
__global__ void prep_B_kernel() {
    int tb = blockIdx.x;                 // nc*8 + kk
    int nc = tb >> 3, kk = tb & 7;
    size_t base = (size_t)tb * 65536;
    for (int q = threadIdx.x; q < 2048; q += 256) {
        int m = q >> 3, c = q & 7;
        const float* row = g_emb + (size_t)(nc * 256 + m) * SEM_DIMV + kk * 64 + c * 8;
        uint32_t hp[4], lp[4];
#pragma unroll
        for (int i = 0; i < 4; i++) split_pack(row[2*i], row[2*i+1], hp[i], lp[i]);
        uint32_t off = (uint32_t)m * 128 + ((uint32_t)(c ^ (m & 7)) << 4);
        *(uint4*)(g_B + base + off)         = make_uint4(hp[0], hp[1], hp[2], hp[3]);
        *(uint4*)(g_B + base + 32768 + off) = make_uint4(lp[0], lp[1], lp[2], lp[3]);
    }
}

// ---------------------------------------------------------------------------
// prep_A: 64-row tiles. grid = N_TILES*8; per block: 64 rows x 64 k.
// ---------------------------------------------------------------------------
__global__ __launch_bounds__(256)
void prep_A_kernel(const float* __restrict__ x) {
    __shared__ float s[64 * 65];
    int tile = blockIdx.x >> 3, kk = blockIdx.x & 7;
    int b = tile >> 6, t0 = (tile & 63) * 64;
    int tid = threadIdx.x;
#pragma unroll
    for (int i = 0; i < 16; i++) {
        int idx = i * 256 + tid;
        int k = idx >> 6, m = idx & 63;
        s[k * 65 + m] = x[((size_t)(b * DTOT + kk * 64 + k)) * TT + t0 + m];
    }
    __syncthreads();
    size_t base = (size_t)blockIdx.x * 16384;
    for (int q = tid; q < 512; q += 256) {
        int m = q >> 3, c = q & 7;
        uint32_t hp[4], lp[4];
#pragma unroll
        for (int i = 0; i < 4; i++)
            split_pack(s[(c * 8 + 2*i) * 65 + m], s[(c * 8 + 2*i + 1) * 65 + m], hp[i], lp[i]);
        uint32_t off = (uint32_t)m * 128 + ((uint32_t)(c ^ (m & 7)) << 4);
        *(uint4*)(g_A + base + off)        = make_uint4(hp[0], hp[1], hp[2], hp[3]);
        *(uint4*)(g_A + base + 8192 + off) = make_uint4(lp[0], lp[1], lp[2], lp[3]);
    }
}

// ---------------------------------------------------------------------------
// sem_mma: 64-row tiles, warp tile 32x64, warp-scoped slot release
// ---------------------------------------------------------------------------
__global__ __launch_bounds__(256, 1)
void sem_mma_kernel(const float* __restrict__ x,
                    const float* __restrict__ probs_sem,
                    float* __restrict__ outq,
                    float* __restrict__ outc) {
    extern __shared__ unsigned char dynraw[];
    __shared__ __align__(8) unsigned long long bars[4];   // full0,full1,empty0,empty1
    __shared__ int codes_s[TILE_M];

    uint32_t raw = smem_u32(dynraw);
    uint32_t abase = (raw + 1023u) & ~1023u;
    float* esq_s = (float*)(dynraw + (abase - raw) + ESQ_OFF);
    float* smbuf = (float*)(dynraw + (abase - raw));
    uint32_t barF[2] = { smem_u32(&bars[0]), smem_u32(&bars[1]) };
    uint32_t barE[2] = { smem_u32(&bars[2]), smem_u32(&bars[3]) };

    int tid = threadIdx.x;
    int lane = tid & 31;
    int wid = tid >> 5;
    int warpM = wid >> 2, warpN = wid & 3;     // 2 x 4

    int tile = blockIdx.x;
    int b = tile >> 6, t0 = (tile & 63) * 64;

    if (tid == 0) {
        mbar_init(barF[0], 1); mbar_init(barF[1], 1);
        mbar_init(barE[0], 8); mbar_init(barE[1], 8);
    }
    for (int i = tid; i < SEM_SIZEV; i += 256) esq_s[i] = g_esq[i];
    __syncthreads();

    const unsigned char* srcA = g_A + (size_t)tile * (8 * 16384);

    if (tid == 0) {
#pragma unroll
        for (int s = 0; s < 2; s++) {
            mbar_expect_tx(barF[s], SLOT_BYTES);
            bulk_g2s(abase + s * SLOT_BYTES, srcA + (size_t)s * 16384, 16384, barF[s]);
            bulk_g2s(abase + s * SLOT_BYTES + 16384, g_B + (size_t)s * 65536, 65536, barF[s]);
        }
    }

    // ldmatrix geometry
    uint32_t sw = lane & 7;
    uint32_t aRowOff = (uint32_t)(warpM * 32 + (lane & 15)) * 128;
    uint32_t aAdd = lane >> 4;
    uint32_t bRowOff = (uint32_t)(warpN * 64 + (lane & 7) + ((lane & 16) >> 1)) * 128;
    uint32_t bAdd = (lane >> 3) & 1;

    float acc[2][8][4];
    float bestv[2][2];
    int   besti[2][2];
#pragma unroll
    for (int mi = 0; mi < 2; mi++)
#pragma unroll
        for (int h = 0; h < 2; h++) { bestv[mi][h] = 3.4e38f; besti[mi][h] = 0; }

    for (int s = 0; s < NC_COUNT * KK_COUNT; s++) {
        int kk = s & 7, slot = s & 1;
        mbar_wait(barF[slot], (s >> 1) & 1);
        uint32_t sb = abase + slot * SLOT_BYTES;

        if (kk == 0) {
#pragma unroll
            for (int mi = 0; mi < 2; mi++)
#pragma unroll
                for (int nf = 0; nf < 8; nf++)
#pragma unroll
                    for (int e = 0; e < 4; e++) acc[mi][nf][e] = 0.0f;
        }

#pragma unroll 1
        for (int pass = 0; pass < 3; pass++) {
            uint32_t aoff = sb + ((pass == 2) ? 8192u : 0u);
            uint32_t boff = sb + 16384u + ((pass == 1) ? 32768u : 0u);
#pragma unroll
            for (int j = 0; j < 4; j++) {
                uint32_t ar[2][4], br[4][4];
                uint32_t ca = (uint32_t)(((2 * j + aAdd) ^ sw) << 4);
                uint32_t cb = (uint32_t)(((2 * j + bAdd) ^ sw) << 4);
#pragma unroll
                for (int mi = 0; mi < 2; mi++)
                    LDSM4(ar[mi][0], ar[mi][1], ar[mi][2], ar[mi][3],
                          aoff + aRowOff + mi * 2048 + ca);
#pragma unroll
                for (int nf2 = 0; nf2 < 4; nf2++)
                    LDSM4(br[nf2][0], br[nf2][1], br[nf2][2], br[nf2][3],
                          boff + bRowOff + nf2 * 2048 + cb);
#pragma unroll
                for (int mi = 0; mi < 2; mi++)
#pragma unroll
                    for (int nf2 = 0; nf2 < 4; nf2++) {
                        MMA16816(acc[mi][2 * nf2],     ar[mi][0], ar[mi][1], ar[mi][2], ar[mi][3],
                                 br[nf2][0], br[nf2][1]);
                        MMA16816(acc[mi][2 * nf2 + 1], ar[mi][0], ar[mi][1], ar[mi][2], ar[mi][3],
                                 br[nf2][2], br[nf2][3]);
                    }
            }
        }
        // warp done reading slot smem -> release
        if (lane == 0) mbar_arrive(barE[slot]);

        // producer: refill this slot for s+2 once all warps released it
        if (tid == 0 && s + 2 < NC_COUNT * KK_COUNT) {
            mbar_wait(barE[slot], (s >> 1) & 1);
            int s2 = s + 2, nc2 = s2 >> 3, kk2 = s2 & 7;
            mbar_expect_tx(barF[slot], SLOT_BYTES);
            bulk_g2s(sb, srcA + (size_t)kk2 * 16384, 16384, barF[slot]);
            bulk_g2s(sb + 16384, g_B + (size_t)(nc2 * 8 + kk2) * 65536, 65536, barF[slot]);
        }

        if (kk == 7) {                     // score this 256-code chunk
            int nc = s >> 3;
            int cbase = nc * 256 + warpN * 64 + (lane & 3) * 2;
#pragma unroll
            for (int nf = 0; nf < 8; nf++) {
                float eq0 = esq_s[cbase + nf * 8 + 0];
                float eq1 = esq_s[cbase + nf * 8 + 1];
#pragma unroll
                for (int mi = 0; mi < 2; mi++) {
                    float s00 = eq0 - 2.0f * acc[mi][nf][0];
                    float s01 = eq1 - 2.0f * acc[mi][nf][1];
                    float s10 = eq0 - 2.0f * acc[mi][nf][2];
                    float s11 = eq1 - 2.0f * acc[mi][nf][3];
                    int c0 = cbase + nf * 8, c1 = c0 + 1;
                    if (s00 < bestv[mi][0]) { bestv[mi][0] = s00; besti[mi][0] = c0; }
                    if (s01 < bestv[mi][0]) { bestv[mi][0] = s01; besti[mi][0] = c1; }
                    if (s10 < bestv[mi][1]) { bestv[mi][1] = s10; besti[mi][1] = c0; }
                    if (s11 < bestv[mi][1]) { bestv[mi][1] = s11; besti[mi][1] = c1; }
                }
            }
        }
    }

    // cross-lane reduce (lanes sharing a row differ only in lane&3)
    __syncthreads();
    float* redV = esq_s;                   // [64][4]
    int*   redI = (int*)(esq_s + 256);     // [64][4]
#pragma unroll
    for (int mi = 0; mi < 2; mi++)
#pragma unroll
        for (int h = 0; h < 2; h++) {
            float v = bestv[mi][h];
            int   i = besti[mi][h];
#pragma unroll
            for (int off = 1; off <= 2; off <<= 1) {
                float ov = __shfl_xor_sync(0xffffffffu, v, off);
                int   oi = __shfl_xor_sync(0xffffffffu, i, off);
                if (ov < v || (ov == v && oi < i)) { v = ov; i = oi; }
            }
            if ((lane & 3) == 0) {
                int row = warpM * 32 + mi * 16 + h * 8 + (lane >> 2);
                redV[row * 4 + warpN] = v;
                redI[row * 4 + warpN] = i;
            }
        }
    __syncthreads();
    if (tid < TILE_M) {
        float best = redV[tid * 4];
        int   bst  = redI[tid * 4];
#pragma unroll
        for (int w = 1; w < 4; w++) {
            float v = redV[tid * 4 + w];
            int   i = redI[tid * 4 + w];
            if (v < best || (v == best && i < bst)) { best = v; bst = i; }
        }
        codes_s[tid] = bst;
        outc[(size_t)b * 33 * TT + t0 + tid] = (float)bst;
    }
    __syncthreads();

    // ---------------- output phase ----------------
    float psem = probs_sem[b];
    const float* xb = x + (size_t)b * DTOT * TT + t0;
    float* outqb = outq + (size_t)b * DTOT * TT + t0;

    if (psem < 0.5f) {
        int r = tid >> 2, q = tid & 3;       // 4 threads per row
        const float* erow = g_emb + (size_t)codes_s[r] * SEM_DIMV;
        for (int dc = 0; dc < SEM_DIMV; dc += 64) {
            __syncthreads();
#pragma unroll
            for (int i = 0; i < 4; i++) {
                int dd = q * 16 + i * 4;
                float4 v = *(const float4*)(erow + dc + dd);
                smbuf[(dd + 0) * 68 + r] = v.x;
                smbuf[(dd + 1) * 68 + r] = v.y;
                smbuf[(dd + 2) * 68 + r] = v.z;
                smbuf[(dd + 3) * 68 + r] = v.w;
            }
            __syncthreads();
#pragma unroll
            for (int it = 0; it < 4; it++) {
                int idx = it * 256 + tid;
                int k = idx >> 4, r4 = (idx & 15) << 2;
                *(float4*)(outqb + (size_t)(dc + k) * TT + r4) = *(float4*)&smbuf[k * 68 + r4];
            }
        }
    } else {
        for (int it = 0; it < 32; it++) {
            int idx = it * 256 + tid;
            int k = idx >> 4, r4 = (idx & 15) << 2;
            *(float4*)(outqb + (size_t)k * TT + r4) = *(const float4*)(xb + (size_t)k * TT + r4);
        }
    }
}

// ---------------------------------------------------------------------------
__global__ void aco_kernel(const float* __restrict__ x,
                           const float* __restrict__ noise,
                           const float* __restrict__ probs_aco,
                           float* __restrict__ outq,
                           float* __restrict__ outc) {
    int idx = blockIdx.x * blockDim.x + threadIdx.x;
    int t = idx & 4095;
    int rj = idx >> 12;
    int b = rj >> 5, j = rj & 31;

    float a = x[((size_t)b * DTOT + SEM_DIMV + j) * TT + t];
    float zb = tanhf(a) * HALFV;
    float pa = probs_aco[b];
    float zout;
    if (pa < 0.5f) {
        zout = rintf(zb);
    } else if (pa < 0.75f) {
        float ns = (noise[(size_t)rj * TT + t] * 2.0f - 1.0f) * (HALFV / 9.0f);
        zout = fminf(fmaxf(zb + ns, -HALFV), HALFV);
    } else {
        zout = zb;
    }
    float code = fminf(fmaxf(rintf(zout + HALFV), 0.0f), 8.0f);
    outq[((size_t)b * DTOT + SEM_DIMV + j) * TT + t] = zout * 0.25f;
    outc[((size_t)b * 33 + 1 + j) * TT + t] = code;
}

// ---------------------------------------------------------------------------
extern "C" void kernel_launch(void* const* d_in, const int* in_sizes, int n_in,
                              void* d_out, int out_size) {
    const float* x     = (const float*)d_in[0];
    const float* esum  = (const float*)d_in[1];
    const float* usage = (const float*)d_in[2];
    const float* noise = (const float*)d_in[3];
    const float* psem  = (const float*)d_in[4];
    const float* paco  = (const float*)d_in[5];

    float* outq = (float*)d_out;
    float* outc = outq + (size_t)BB * DTOT * TT;

    cudaFuncSetAttribute(sem_mma_kernel,
                         cudaFuncAttributeMaxDynamicSharedMemorySize, DYN_BYTES);

    prep_emb_kernel<<<SEM_SIZEV, 128>>>(esum, usage);
    prep_B_kernel<<<64, 256>>>();
    prep_A_kernel<<<N_TILES * 8, 256>>>(x);
    sem_mma_kernel<<<N_TILES, 256, DYN_BYTES>>>(x, psem, outq, outc);
    aco_kernel<<<(BB * ACO_DIMV * TT) / 256, 256>>>(x, noise, paco, outq, outc);
}

// round 5
// speedup vs baseline: 6.2434x; 1.6701x over previous
#include <cuda_runtime.h>
#include <cuda_bf16.h>
#include <cstdint>

#define SEM_DIMV 512
#define SEM_SIZEV 2048
#define ACO_DIMV 32
#define BB 16
#define TT 4096
#define NROWS (BB*TT)
#define DTOT 544
#define HALFV 4.0f
#define EPSV 1e-5f

#define TILE_M 64
#define N_TILES (NROWS/TILE_M)   // 1024
#define NC_COUNT 8
#define KK_COUNT 8
#define NSLOT 4
// slot: A hi 8KB @0, B hi 32KB @8192
#define SLOT_BYTES 40960
#define ESQ_OFF (NSLOT*SLOT_BYTES)
#define DYN_BYTES (ESQ_OFF + 8192 + 1024)
#define DELTA_C 0.0088f

__device__ __align__(128) unsigned char g_A[N_TILES * 8 * 8192];   // 64MB
__device__ __align__(128) unsigned char g_B[64 * 32768];           // 2MB
__device__ float g_emb[SEM_SIZEV * SEM_DIMV];
__device__ float g_esq[SEM_SIZEV];
__device__ float g_candV[(size_t)NROWS * 32];                      // 8MB
__device__ int   g_candI[(size_t)NROWS * 32];                      // 8MB

// ------------------------------------------------------------------ helpers
__device__ __forceinline__ uint32_t smem_u32(const void* p) {
    uint32_t a;
    asm("{ .reg .u64 t; cvta.to.shared.u64 t, %1; cvt.u32.u64 %0, t; }" : "=r"(a) : "l"(p));
    return a;
}
__device__ __forceinline__ void mbar_init(uint32_t a, uint32_t cnt) {
    asm volatile("mbarrier.init.shared.b64 [%0], %1;" :: "r"(a), "r"(cnt) : "memory");
}
__device__ __forceinline__ void mbar_expect_tx(uint32_t a, uint32_t bytes) {
    asm volatile("mbarrier.arrive.expect_tx.shared.b64 _, [%0], %1;" :: "r"(a), "r"(bytes) : "memory");
}
__device__ __forceinline__ void mbar_arrive(uint32_t a) {
    asm volatile("mbarrier.arrive.shared.b64 _, [%0];" :: "r"(a) : "memory");
}
__device__ __forceinline__ void mbar_wait(uint32_t a, uint32_t parity) {
    asm volatile(
        "{\n\t.reg .pred P;\n\t"
        "W_%=:\n\t"
        "mbarrier.try_wait.parity.acquire.cta.shared::cta.b64 P, [%0], %1, 0x989680;\n\t"
        "@!P bra W_%=;\n\t}"
        :: "r"(a), "r"(parity) : "memory");
}
__device__ __forceinline__ void bulk_g2s(uint32_t dst, const void* src, uint32_t bytes, uint32_t mbar) {
    asm volatile("cp.async.bulk.shared::cluster.global.mbarrier::complete_tx::bytes [%0], [%1], %2, [%3];"
        :: "r"(dst), "l"(src), "r"(bytes), "r"(mbar) : "memory");
}

#define LDSM4(R0,R1,R2,R3,ADDR) \
    asm volatile("ldmatrix.sync.aligned.m8n8.x4.shared.b16 {%0,%1,%2,%3}, [%4];" \
        : "=r"(R0), "=r"(R1), "=r"(R2), "=r"(R3) : "r"(ADDR))

#define MMA16816(D, A0,A1,A2,A3, B0,B1) \
    asm volatile("mma.sync.aligned.m16n8k16.row.col.f32.bf16.bf16.f32 " \
        "{%0,%1,%2,%3},{%4,%5,%6,%7},{%8,%9},{%0,%1,%2,%3};" \
        : "+f"((D)[0]), "+f"((D)[1]), "+f"((D)[2]), "+f"((D)[3]) \
        : "r"(A0), "r"(A1), "r"(A2), "r"(A3), "r"(B0), "r"(B1))

__device__ __forceinline__ uint32_t pack_hi(float f0, float f1) {
    __nv_bfloat16 h0 = __float2bfloat16(f0);
    __nv_bfloat16 h1 = __float2bfloat16(f1);
    return (uint32_t)__bfloat16_as_ushort(h0) | ((uint32_t)__bfloat16_as_ushort(h1) << 16);
}
__device__ __forceinline__ void top2_ins(float v, int i, float* V, int* I) {
    if (v < V[0]) { V[1] = V[0]; I[1] = I[0]; V[0] = v; I[0] = i; }
    else if (v < V[1]) { V[1] = v; I[1] = i; }
}

// ---------------------------------------------------------------------------
__global__ void prep_emb_kernel(const float* __restrict__ esum,
                                const float* __restrict__ usage) {
    int c = blockIdx.x, tid = threadIdx.x;
    float inv = 1.0f / fmaxf(usage[c], EPSV);
    float acc = 0.0f;
#pragma unroll
    for (int i = 0; i < 4; i++) {
        int d = tid + i * 128;
        float e = esum[c * SEM_DIMV + d] * inv;
        g_emb[c * SEM_DIMV + d] = e;
        acc += e * e;
    }
    __shared__ float red[128];
    red[tid] = acc;
    __syncthreads();
    if (tid < 64) red[tid] += red[tid + 64];
    __syncthreads();
    if (tid < 32) {
        float v = red[tid] + red[tid + 32];
#pragma unroll
        for (int o = 16; o > 0; o >>= 1) v += __shfl_down_sync(0xffffffffu, v, o);
        if (tid == 0) g_esq[c] = v;
    }
}

// ---------------------------------------------------------------------------
__global__ void prep_B_kernel() {
    int tb = blockIdx.x;                 // nc*8 + kk
    int nc = tb >> 3, kk = tb & 7;
    size_t base = (size_t)tb * 32768;
    for (int q = threadIdx.x; q < 2048; q += 256) {
        int m = q >> 3, c = q & 7;
        const float* row = g_emb + (size_t)(nc * 256 + m) * SEM_DIMV + kk * 64 + c * 8;
        uint32_t hp[4];
#pragma unroll
        for (int i = 0; i < 4; i++) hp[i] = pack_hi(row[2*i], row[2*i+1]);
        uint32_t off = (uint32_t)m * 128 + ((uint32_t)(c ^ (m & 7)) << 4);
        *(uint4*)(g_B + base + off) = make_uint4(hp[0], hp[1], hp[2], hp[3]);
    }
}

// ---------------------------------------------------------------------------
__global__ __launch_bounds__(256)
void prep_A_kernel(const float* __restrict__ x) {
    __shared__ float s[64 * 65];
    int tile = blockIdx.x >> 3, kk = blockIdx.x & 7;
    int b = tile >> 6, t0 = (tile & 63) * 64;
    int tid = threadIdx.x;
#pragma unroll
    for (int i = 0; i < 16; i++) {
        int idx = i * 256 + tid;
        int k = idx >> 6, m = idx & 63;
        s[k * 65 + m] = x[((size_t)(b * DTOT + kk * 64 + k)) * TT + t0 + m];
    }
    __syncthreads();
    size_t base = (size_t)blockIdx.x * 8192;
    for (int q = tid; q < 512; q += 256) {
        int m = q >> 3, c = q & 7;
        uint32_t hp[4];
#pragma unroll
        for (int i = 0; i < 4; i++)
            hp[i] = pack_hi(s[(c * 8 + 2*i) * 65 + m], s[(c * 8 + 2*i + 1) * 65 + m]);
        uint32_t off = (uint32_t)m * 128 + ((uint32_t)(c ^ (m & 7)) << 4);
        *(uint4*)(g_A + base + off) = make_uint4(hp[0], hp[1], hp[2], hp[3]);
    }
}

// ---------------------------------------------------------------------------
// coarse: 1-pass hi*hi GEMM, per-thread top-2 per row-slot -> 32 cand/row
// ---------------------------------------------------------------------------
__global__ __launch_bounds__(256, 1)
void coarse_kernel() {
    extern __shared__ unsigned char dynraw[];
    __shared__ __align__(8) unsigned long long bars[2 * NSLOT];

    uint32_t raw = smem_u32(dynraw);
    uint32_t abase = (raw + 1023u) & ~1023u;
    float* esq_s = (float*)(dynraw + (abase - raw) + ESQ_OFF);
    uint32_t barF[NSLOT], barE[NSLOT];
#pragma unroll
    for (int i = 0; i < NSLOT; i++) {
        barF[i] = smem_u32(&bars[i]);
        barE[i] = smem_u32(&bars[NSLOT + i]);
    }

    int tid = threadIdx.x;
    int lane = tid & 31;
    int wid = tid >> 5;
    int warpM = wid >> 2, warpN = wid & 3;
    int tile = blockIdx.x;

    if (tid == 0) {
#pragma unroll
        for (int i = 0; i < NSLOT; i++) { mbar_init(barF[i], 1); mbar_init(barE[i], 8); }
    }
    for (int i = tid; i < SEM_SIZEV; i += 256) esq_s[i] = g_esq[i];
    __syncthreads();

    const unsigned char* srcA = g_A + (size_t)tile * (8 * 8192);

    if (tid == 0) {
#pragma unroll
        for (int s = 0; s < NSLOT; s++) {
            mbar_expect_tx(barF[s], SLOT_BYTES);
            bulk_g2s(abase + s * SLOT_BYTES, srcA + (size_t)s * 8192, 8192, barF[s]);
            bulk_g2s(abase + s * SLOT_BYTES + 8192, g_B + (size_t)s * 32768, 32768, barF[s]);
        }
    }

    uint32_t sw = lane & 7;
    uint32_t aRowOff = (uint32_t)(warpM * 32 + (lane & 15)) * 128;
    uint32_t aAdd = lane >> 4;
    uint32_t bRowOff = (uint32_t)(warpN * 64 + (lane & 7) + ((lane & 16) >> 1)) * 128;
    uint32_t bAdd = (lane >> 3) & 1;

    float acc[2][8][4];
    float tV[2][2][2];
    int   tI[2][2][2];
#pragma unroll
    for (int mi = 0; mi < 2; mi++)
#pragma unroll
        for (int h = 0; h < 2; h++) {
            tV[mi][h][0] = tV[mi][h][1] = 3.4e38f;
            tI[mi][h][0] = tI[mi][h][1] = 0;
        }

    for (int s = 0; s < NC_COUNT * KK_COUNT; s++) {
        int kk = s & 7, slot = s & (NSLOT - 1);
        mbar_wait(barF[slot], (s >> 2) & 1);
        uint32_t sb = abase + slot * SLOT_BYTES;

        if (kk == 0) {
#pragma unroll
            for (int mi = 0; mi < 2; mi++)
#pragma unroll
                for (int nf = 0; nf < 8; nf++)
#pragma unroll
                    for (int e = 0; e < 4; e++) acc[mi][nf][e] = 0.0f;
        }

#pragma unroll
        for (int j = 0; j < 4; j++) {
            uint32_t ar[2][4], br[4][4];
            uint32_t ca = (uint32_t)(((2 * j + aAdd) ^ sw) << 4);
            uint32_t cb = (uint32_t)(((2 * j + bAdd) ^ sw) << 4);
#pragma unroll
            for (int mi = 0; mi < 2; mi++)
                LDSM4(ar[mi][0], ar[mi][1], ar[mi][2], ar[mi][3],
                      sb + aRowOff + mi * 2048 + ca);
#pragma unroll
            for (int nf2 = 0; nf2 < 4; nf2++)
                LDSM4(br[nf2][0], br[nf2][1], br[nf2][2], br[nf2][3],
                      sb + 8192 + bRowOff + nf2 * 2048 + cb);
#pragma unroll
            for (int mi = 0; mi < 2; mi++)
#pragma unroll
                for (int nf2 = 0; nf2 < 4; nf2++) {
                    MMA16816(acc[mi][2 * nf2],     ar[mi][0], ar[mi][1], ar[mi][2], ar[mi][3],
                             br[nf2][0], br[nf2][1]);
                    MMA16816(acc[mi][2 * nf2 + 1], ar[mi][0], ar[mi][1], ar[mi][2], ar[mi][3],
                             br[nf2][2], br[nf2][3]);
                }
        }
        if (lane == 0) mbar_arrive(barE[slot]);

        if (tid == 0 && s + NSLOT < NC_COUNT * KK_COUNT) {
            mbar_wait(barE[slot], (s >> 2) & 1);
            int s2 = s + NSLOT, nc2 = s2 >> 3, kk2 = s2 & 7;
            mbar_expect_tx(barF[slot], SLOT_BYTES);
            bulk_g2s(sb, srcA + (size_t)kk2 * 8192, 8192, barF[slot]);
            bulk_g2s(sb + 8192, g_B + (size_t)(nc2 * 8 + kk2) * 32768, 32768, barF[slot]);
        }

        if (kk == 7) {
            int nc = s >> 3;
            int cbase = nc * 256 + warpN * 64 + (lane & 3) * 2;
#pragma unroll
            for (int nf = 0; nf < 8; nf++) {
                float eq0 = esq_s[cbase + nf * 8 + 0];
                float eq1 = esq_s[cbase + nf * 8 + 1];
                int c0 = cbase + nf * 8, c1 = c0 + 1;
#pragma unroll
                for (int mi = 0; mi < 2; mi++) {
                    top2_ins(eq0 - 2.0f * acc[mi][nf][0], c0, tV[mi][0], tI[mi][0]);
                    top2_ins(eq1 - 2.0f * acc[mi][nf][1], c1, tV[mi][0], tI[mi][0]);
                    top2_ins(eq0 - 2.0f * acc[mi][nf][2], c0, tV[mi][1], tI[mi][1]);
                    top2_ins(eq1 - 2.0f * acc[mi][nf][3], c1, tV[mi][1], tI[mi][1]);
                }
            }
        }
    }

    // write 32 candidates per row
    int slotIdx = (warpN * 4 + (lane & 3)) * 2;
#pragma unroll
    for (int mi = 0; mi < 2; mi++)
#pragma unroll
        for (int h = 0; h < 2; h++) {
            int r = tile * 64 + warpM * 32 + mi * 16 + h * 8 + (lane >> 2);
            size_t base = (size_t)r * 32 + slotIdx;
            g_candV[base]     = tV[mi][h][0];
            g_candV[base + 1] = tV[mi][h][1];
            g_candI[base]     = tI[mi][h][0];
            g_candI[base + 1] = tI[mi][h][1];
        }
}

// ---------------------------------------------------------------------------
// rescore: warp per row; margin filter + exact fp32 rescore; sem output
// block = 1024 threads = 32 warps = 32 consecutive t rows of one batch b
// ---------------------------------------------------------------------------
#define XS_PITCH 513
#define DYN_RESCORE (32 * XS_PITCH * 4)

__global__ __launch_bounds__(1024)
void rescore_kernel(const float* __restrict__ x,
                    const float* __restrict__ probs_sem,
                    float* __restrict__ outq,
                    float* __restrict__ outc) {
    extern __shared__ float xs[];
    __shared__ int codes_s[32];

    int tid = threadIdx.x;
    int lane = tid & 31;
    int w = tid >> 5;
    int b = blockIdx.x >> 7;
    int t0 = (blockIdx.x & 127) * 32;

    const float* xb = x + (size_t)b * DTOT * TT + t0;

    // stage x rows: xs[t][d] with pitch 513 (conflict-free both phases)
#pragma unroll
    for (int it = 0; it < 16; it++) {
        int idx = it * 1024 + tid;
        int d = idx >> 5, t = idx & 31;
        xs[t * XS_PITCH + d] = xb[(size_t)d * TT + t];
    }
    __syncthreads();

    int r = blockIdx.x * 32 + w;          // global row = b*4096 + t0 + w
    float candV = g_candV[(size_t)r * 32 + lane];
    int   candI = g_candI[(size_t)r * 32 + lane];
    float candE = g_esq[candI];

    // row |x|^2
    float xsq = 0.0f;
#pragma unroll
    for (int i = 0; i < 16; i++) {
        float v = xs[w * XS_PITCH + i * 32 + lane];
        xsq += v * v;
    }
#pragma unroll
    for (int o = 16; o > 0; o >>= 1) xsq += __shfl_xor_sync(0xffffffffu, xsq, o);

    float delta = DELTA_C * sqrtf(xsq * candE);
    float ub = candV + delta;
#pragma unroll
    for (int o = 16; o > 0; o >>= 1) ub = fminf(ub, __shfl_xor_sync(0xffffffffu, ub, o));
    unsigned pm = __ballot_sync(0xffffffffu, candV - delta <= ub);

    float bestd = 3.4e38f;
    int bestc = SEM_SIZEV;
    while (pm) {
        int p = __ffs(pm) - 1;
        pm &= pm - 1;
        int c = __shfl_sync(0xffffffffu, candI, p);
        float eq = __shfl_sync(0xffffffffu, candE, p);
        const float* er = g_emb + (size_t)c * SEM_DIMV;
        float dot = 0.0f;
#pragma unroll
        for (int i = 0; i < 16; i++)
            dot += xs[w * XS_PITCH + i * 32 + lane] * er[i * 32 + lane];
#pragma unroll
        for (int o = 16; o > 0; o >>= 1) dot += __shfl_xor_sync(0xffffffffu, dot, o);
        float d2 = eq - 2.0f * dot;
        if (d2 < bestd || (d2 == bestd && c < bestc)) { bestd = d2; bestc = c; }
    }
    if (lane == 0) {
        codes_s[w] = bestc;
        outc[(size_t)b * 33 * TT + t0 + w] = (float)bestc;
    }
    __syncthreads();

    // sem output
    float psem = probs_sem[b];
    float* outqb = outq + (size_t)b * DTOT * TT + t0;
    if (psem < 0.5f) {
        // restage emb rows over xs, then same write pattern
        int c = codes_s[w];
        const float* er = g_emb + (size_t)c * SEM_DIMV;
        __syncthreads();
#pragma unroll
        for (int i = 0; i < 16; i++)
            xs[w * XS_PITCH + i * 32 + lane] = er[i * 32 + lane];
        __syncthreads();
    }
#pragma unroll
    for (int it = 0; it < 16; it++) {
        int idx = it * 1024 + tid;
        int d = idx >> 5, t = idx & 31;
        outqb[(size_t)d * TT + t] = xs[t * XS_PITCH + d];
    }
}

// ---------------------------------------------------------------------------
__global__ void aco_kernel(const float* __restrict__ x,
                           const float* __restrict__ noise,
                           const float* __restrict__ probs_aco,
                           float* __restrict__ outq,
                           float* __restrict__ outc) {
    int idx = blockIdx.x * blockDim.x + threadIdx.x;
    int t = idx & 4095;
    int rj = idx >> 12;
    int b = rj >> 5, j = rj & 31;

    float a = x[((size_t)b * DTOT + SEM_DIMV + j) * TT + t];
    float zb = tanhf(a) * HALFV;
    float pa = probs_aco[b];
    float zout;
    if (pa < 0.5f) {
        zout = rintf(zb);
    } else if (pa < 0.75f) {
        float ns = (noise[(size_t)rj * TT + t] * 2.0f - 1.0f) * (HALFV / 9.0f);
        zout = fminf(fmaxf(zb + ns, -HALFV), HALFV);
    } else {
        zout = zb;
    }
    float code = fminf(fmaxf(rintf(zout + HALFV), 0.0f), 8.0f);
    outq[((size_t)b * DTOT + SEM_DIMV + j) * TT + t] = zout * 0.25f;
    outc[((size_t)b * 33 + 1 + j) * TT + t] = code;
}

// ---------------------------------------------------------------------------
extern "C" void kernel_launch(void* const* d_in, const int* in_sizes, int n_in,
                              void* d_out, int out_size) {
    const float* x     = (const float*)d_in[0];
    const float* esum  = (const float*)d_in[1];
    const float* usage = (const float*)d_in[2];
    const float* noise = (const float*)d_in[3];
    const float* psem  = (const float*)d_in[4];
    const float* paco  = (const float*)d_in[5];

    float* outq = (float*)d_out;
    float* outc = outq + (size_t)BB * DTOT * TT;

    cudaFuncSetAttribute(coarse_kernel,
                         cudaFuncAttributeMaxDynamicSharedMemorySize, DYN_BYTES);
    cudaFuncSetAttribute(rescore_kernel,
                         cudaFuncAttributeMaxDynamicSharedMemorySize, DYN_RESCORE);

    prep_emb_kernel<<<SEM_SIZEV, 128>>>(esum, usage);
    prep_B_kernel<<<64, 256>>>();
    prep_A_kernel<<<N_TILES * 8, 256>>>(x);
    coarse_kernel<<<N_TILES, 256, DYN_BYTES>>>();
    rescore_kernel<<<NROWS / 32, 1024, DYN_RESCORE>>>(x, psem, outq, outc);
    aco_kernel<<<(BB * ACO_DIMV * TT) / 256, 256>>>(x, noise, paco, outq, outc);
}

// round 6
// speedup vs baseline: 7.0621x; 1.1311x over previous
#include <cuda_runtime.h>
#include <cuda_bf16.h>
#include <cstdint>

#define SEM_DIMV 512
#define SEM_SIZEV 2048
#define ACO_DIMV 32
#define BB 16
#define TT 4096
#define NROWS (BB*TT)
#define DTOT 544
#define HALFV 4.0f
#define EPSV 1e-5f

#define TILE_M 64
#define N_TILES (NROWS/TILE_M)   // 1024
#define NC_COUNT 8
#define KK_COUNT 8
#define NSLOT 2
// slot: A hi 8KB @0, B hi 32KB @8192
#define SLOT_BYTES 40960
#define ESQ_OFF (NSLOT*SLOT_BYTES)
#define DYN_BYTES (ESQ_OFF + 8192 + 1024)   // ~90KB -> 2 CTAs/SM
#define DELTA_C 0.0088f

__device__ __align__(128) unsigned char g_A[N_TILES * 8 * 8192];   // 64MB
__device__ __align__(128) unsigned char g_B[64 * 32768];           // 2MB
__device__ float g_emb[SEM_SIZEV * SEM_DIMV];
__device__ float g_esq[SEM_SIZEV];
__device__ float g_candV[(size_t)NROWS * 32];                      // 8MB
__device__ int   g_candI[(size_t)NROWS * 32];                      // 8MB

// ------------------------------------------------------------------ helpers
__device__ __forceinline__ uint32_t smem_u32(const void* p) {
    uint32_t a;
    asm("{ .reg .u64 t; cvta.to.shared.u64 t, %1; cvt.u32.u64 %0, t; }" : "=r"(a) : "l"(p));
    return a;
}
__device__ __forceinline__ void mbar_init(uint32_t a, uint32_t cnt) {
    asm volatile("mbarrier.init.shared.b64 [%0], %1;" :: "r"(a), "r"(cnt) : "memory");
}
__device__ __forceinline__ void mbar_expect_tx(uint32_t a, uint32_t bytes) {
    asm volatile("mbarrier.arrive.expect_tx.shared.b64 _, [%0], %1;" :: "r"(a), "r"(bytes) : "memory");
}
__device__ __forceinline__ void mbar_arrive(uint32_t a) {
    asm volatile("mbarrier.arrive.shared.b64 _, [%0];" :: "r"(a) : "memory");
}
__device__ __forceinline__ void mbar_wait(uint32_t a, uint32_t parity) {
    asm volatile(
        "{\n\t.reg .pred P;\n\t"
        "W_%=:\n\t"
        "mbarrier.try_wait.parity.acquire.cta.shared::cta.b64 P, [%0], %1, 0x989680;\n\t"
        "@!P bra W_%=;\n\t}"
        :: "r"(a), "r"(parity) : "memory");
}
__device__ __forceinline__ void bulk_g2s(uint32_t dst, const void* src, uint32_t bytes, uint32_t mbar) {
    asm volatile("cp.async.bulk.shared::cluster.global.mbarrier::complete_tx::bytes [%0], [%1], %2, [%3];"
        :: "r"(dst), "l"(src), "r"(bytes), "r"(mbar) : "memory");
}

#define LDSM4(R0,R1,R2,R3,ADDR) \
    asm volatile("ldmatrix.sync.aligned.m8n8.x4.shared.b16 {%0,%1,%2,%3}, [%4];" \
        : "=r"(R0), "=r"(R1), "=r"(R2), "=r"(R3) : "r"(ADDR))

#define MMA16816(D, A0,A1,A2,A3, B0,B1) \
    asm volatile("mma.sync.aligned.m16n8k16.row.col.f32.bf16.bf16.f32 " \
        "{%0,%1,%2,%3},{%4,%5,%6,%7},{%8,%9},{%0,%1,%2,%3};" \
        : "+f"((D)[0]), "+f"((D)[1]), "+f"((D)[2]), "+f"((D)[3]) \
        : "r"(A0), "r"(A1), "r"(A2), "r"(A3), "r"(B0), "r"(B1))

__device__ __forceinline__ uint32_t pack_hi(float f0, float f1) {
    __nv_bfloat16 h0 = __float2bfloat16(f0);
    __nv_bfloat16 h1 = __float2bfloat16(f1);
    return (uint32_t)__bfloat16_as_ushort(h0) | ((uint32_t)__bfloat16_as_ushort(h1) << 16);
}
__device__ __forceinline__ void top2_ins(float v, int i, float* V, int* I) {
    if (v < V[0]) { V[1] = V[0]; I[1] = I[0]; V[0] = v; I[0] = i; }
    else if (v < V[1]) { V[1] = v; I[1] = i; }
}

// ---------------------------------------------------------------------------
__global__ void prep_emb_kernel(const float* __restrict__ esum,
                                const float* __restrict__ usage) {
    int c = blockIdx.x, tid = threadIdx.x;
    float inv = 1.0f / fmaxf(usage[c], EPSV);
    float acc = 0.0f;
#pragma unroll
    for (int i = 0; i < 4; i++) {
        int d = tid + i * 128;
        float e = esum[c * SEM_DIMV + d] * inv;
        g_emb[c * SEM_DIMV + d] = e;
        acc += e * e;
    }
    __shared__ float red[128];
    red[tid] = acc;
    __syncthreads();
    if (tid < 64) red[tid] += red[tid + 64];
    __syncthreads();
    if (tid < 32) {
        float v = red[tid] + red[tid + 32];
#pragma unroll
        for (int o = 16; o > 0; o >>= 1) v += __shfl_down_sync(0xffffffffu, v, o);
        if (tid == 0) g_esq[c] = v;
    }
}

// ---------------------------------------------------------------------------
__global__ void prep_B_kernel() {
    int tb = blockIdx.x;                 // nc*8 + kk
    int nc = tb >> 3, kk = tb & 7;
    size_t base = (size_t)tb * 32768;
    for (int q = threadIdx.x; q < 2048; q += 256) {
        int m = q >> 3, c = q & 7;
        const float* row = g_emb + (size_t)(nc * 256 + m) * SEM_DIMV + kk * 64 + c * 8;
        uint32_t hp[4];
#pragma unroll
        for (int i = 0; i < 4; i++) hp[i] = pack_hi(row[2*i], row[2*i+1]);
        uint32_t off = (uint32_t)m * 128 + ((uint32_t)(c ^ (m & 7)) << 4);
        *(uint4*)(g_B + base + off) = make_uint4(hp[0], hp[1], hp[2], hp[3]);
    }
}

// ---------------------------------------------------------------------------
__global__ __launch_bounds__(256)
void prep_A_kernel(const float* __restrict__ x) {
    __shared__ float s[64 * 65];
    int tile = blockIdx.x >> 3, kk = blockIdx.x & 7;
    int b = tile >> 6, t0 = (tile & 63) * 64;
    int tid = threadIdx.x;
#pragma unroll
    for (int i = 0; i < 16; i++) {
        int idx = i * 256 + tid;
        int k = idx >> 6, m = idx & 63;
        s[k * 65 + m] = x[((size_t)(b * DTOT + kk * 64 + k)) * TT + t0 + m];
    }
    __syncthreads();
    size_t base = (size_t)blockIdx.x * 8192;
    for (int q = tid; q < 512; q += 256) {
        int m = q >> 3, c = q & 7;
        uint32_t hp[4];
#pragma unroll
        for (int i = 0; i < 4; i++)
            hp[i] = pack_hi(s[(c * 8 + 2*i) * 65 + m], s[(c * 8 + 2*i + 1) * 65 + m]);
        uint32_t off = (uint32_t)m * 128 + ((uint32_t)(c ^ (m & 7)) << 4);
        *(uint4*)(g_A + base + off) = make_uint4(hp[0], hp[1], hp[2], hp[3]);
    }
}

// ---------------------------------------------------------------------------
// coarse: 1-pass hi*hi GEMM, per-thread top-2 per row-slot -> 32 cand/row
// 2 CTAs/SM (reg cap 128, smem ~90KB)
// ---------------------------------------------------------------------------
__global__ __launch_bounds__(256, 2)
void coarse_kernel() {
    extern __shared__ unsigned char dynraw[];
    __shared__ __align__(8) unsigned long long bars[2 * NSLOT];

    uint32_t raw = smem_u32(dynraw);
    uint32_t abase = (raw + 1023u) & ~1023u;
    float* esq_s = (float*)(dynraw + (abase - raw) + ESQ_OFF);
    uint32_t barF[NSLOT], barE[NSLOT];
#pragma unroll
    for (int i = 0; i < NSLOT; i++) {
        barF[i] = smem_u32(&bars[i]);
        barE[i] = smem_u32(&bars[NSLOT + i]);
    }

    int tid = threadIdx.x;
    int lane = tid & 31;
    int wid = tid >> 5;
    int warpM = wid >> 2, warpN = wid & 3;
    int tile = blockIdx.x;

    if (tid == 0) {
#pragma unroll
        for (int i = 0; i < NSLOT; i++) { mbar_init(barF[i], 1); mbar_init(barE[i], 8); }
    }
    for (int i = tid; i < SEM_SIZEV; i += 256) esq_s[i] = g_esq[i];
    __syncthreads();

    const unsigned char* srcA = g_A + (size_t)tile * (8 * 8192);

    if (tid == 0) {
#pragma unroll
        for (int s = 0; s < NSLOT; s++) {
            mbar_expect_tx(barF[s], SLOT_BYTES);
            bulk_g2s(abase + s * SLOT_BYTES, srcA + (size_t)s * 8192, 8192, barF[s]);
            bulk_g2s(abase + s * SLOT_BYTES + 8192, g_B + (size_t)s * 32768, 32768, barF[s]);
        }
    }

    // hoisted ldmatrix geometry
    uint32_t sw = lane & 7;
    uint32_t aRowOff = (uint32_t)(warpM * 32 + (lane & 15)) * 128;
    uint32_t aAdd = lane >> 4;
    uint32_t bRowOff = (uint32_t)(warpN * 64 + (lane & 7) + ((lane & 16) >> 1)) * 128;
    uint32_t bAdd = (lane >> 3) & 1;
    uint32_t caOff[4], cbOff[4];
#pragma unroll
    for (int j = 0; j < 4; j++) {
        caOff[j] = aRowOff + (uint32_t)(((2 * j + aAdd) ^ sw) << 4);
        cbOff[j] = bRowOff + (uint32_t)(((2 * j + bAdd) ^ sw) << 4);
    }

    float acc[2][8][4];
    float tV[2][2][2];
    int   tI[2][2][2];
#pragma unroll
    for (int mi = 0; mi < 2; mi++)
#pragma unroll
        for (int h = 0; h < 2; h++) {
            tV[mi][h][0] = tV[mi][h][1] = 3.4e38f;
            tI[mi][h][0] = tI[mi][h][1] = 0;
        }

    for (int s = 0; s < NC_COUNT * KK_COUNT; s++) {
        int kk = s & 7, slot = s & (NSLOT - 1);
        mbar_wait(barF[slot], (s >> 1) & 1);
        uint32_t sb = abase + slot * SLOT_BYTES;

        if (kk == 0) {
#pragma unroll
            for (int mi = 0; mi < 2; mi++)
#pragma unroll
                for (int nf = 0; nf < 8; nf++)
#pragma unroll
                    for (int e = 0; e < 4; e++) acc[mi][nf][e] = 0.0f;
        }

#pragma unroll
        for (int j = 0; j < 4; j++) {
            uint32_t ar[2][4], br[4][4];
#pragma unroll
            for (int mi = 0; mi < 2; mi++)
                LDSM4(ar[mi][0], ar[mi][1], ar[mi][2], ar[mi][3],
                      sb + caOff[j] + mi * 2048);
#pragma unroll
            for (int nf2 = 0; nf2 < 4; nf2++)
                LDSM4(br[nf2][0], br[nf2][1], br[nf2][2], br[nf2][3],
                      sb + 8192 + cbOff[j] + nf2 * 2048);
#pragma unroll
            for (int mi = 0; mi < 2; mi++)
#pragma unroll
                for (int nf2 = 0; nf2 < 4; nf2++) {
                    MMA16816(acc[mi][2 * nf2],     ar[mi][0], ar[mi][1], ar[mi][2], ar[mi][3],
                             br[nf2][0], br[nf2][1]);
                    MMA16816(acc[mi][2 * nf2 + 1], ar[mi][0], ar[mi][1], ar[mi][2], ar[mi][3],
                             br[nf2][2], br[nf2][3]);
                }
        }
        if (lane == 0) mbar_arrive(barE[slot]);

        if (tid == 0 && s + NSLOT < NC_COUNT * KK_COUNT) {
            mbar_wait(barE[slot], (s >> 1) & 1);
            int s2 = s + NSLOT, nc2 = s2 >> 3, kk2 = s2 & 7;
            mbar_expect_tx(barF[slot], SLOT_BYTES);
            bulk_g2s(sb, srcA + (size_t)kk2 * 8192, 8192, barF[slot]);
            bulk_g2s(sb + 8192, g_B + (size_t)(nc2 * 8 + kk2) * 32768, 32768, barF[slot]);
        }

        if (kk == 7) {
            int nc = s >> 3;
            int cbase = nc * 256 + warpN * 64 + (lane & 3) * 2;
#pragma unroll
            for (int nf = 0; nf < 8; nf++) {
                float eq0 = esq_s[cbase + nf * 8 + 0];
                float eq1 = esq_s[cbase + nf * 8 + 1];
                int c0 = cbase + nf * 8, c1 = c0 + 1;
#pragma unroll
                for (int mi = 0; mi < 2; mi++) {
                    top2_ins(eq0 - 2.0f * acc[mi][nf][0], c0, tV[mi][0], tI[mi][0]);
                    top2_ins(eq1 - 2.0f * acc[mi][nf][1], c1, tV[mi][0], tI[mi][0]);
                    top2_ins(eq0 - 2.0f * acc[mi][nf][2], c0, tV[mi][1], tI[mi][1]);
                    top2_ins(eq1 - 2.0f * acc[mi][nf][3], c1, tV[mi][1], tI[mi][1]);
                }
            }
        }
    }

    // write 32 candidates per row
    int slotIdx = (warpN * 4 + (lane & 3)) * 2;
#pragma unroll
    for (int mi = 0; mi < 2; mi++)
#pragma unroll
        for (int h = 0; h < 2; h++) {
            int r = tile * 64 + warpM * 32 + mi * 16 + h * 8 + (lane >> 2);
            size_t base = (size_t)r * 32 + slotIdx;
            g_candV[base]     = tV[mi][h][0];
            g_candV[base + 1] = tV[mi][h][1];
            g_candI[base]     = tI[mi][h][0];
            g_candI[base + 1] = tI[mi][h][1];
        }
}

// ---------------------------------------------------------------------------
// rescore: warp per row; margin filter + exact fp32 rescore; sem output
// ---------------------------------------------------------------------------
#define XS_PITCH 513
#define DYN_RESCORE (32 * XS_PITCH * 4)

__global__ __launch_bounds__(1024)
void rescore_kernel(const float* __restrict__ x,
                    const float* __restrict__ probs_sem,
                    float* __restrict__ outq,
                    float* __restrict__ outc) {
    extern __shared__ float xs[];
    __shared__ int codes_s[32];

    int tid = threadIdx.x;
    int lane = tid & 31;
    int w = tid >> 5;
    int b = blockIdx.x >> 7;
    int t0 = (blockIdx.x & 127) * 32;

    const float* xb = x + (size_t)b * DTOT * TT + t0;

#pragma unroll
    for (int it = 0; it < 16; it++) {
        int idx = it * 1024 + tid;
        int d = idx >> 5, t = idx & 31;
        xs[t * XS_PITCH + d] = xb[(size_t)d * TT + t];
    }
    __syncthreads();

    int r = blockIdx.x * 32 + w;
    float candV = g_candV[(size_t)r * 32 + lane];
    int   candI = g_candI[(size_t)r * 32 + lane];
    float candE = g_esq[candI];

    float xsq = 0.0f;
#pragma unroll
    for (int i = 0; i < 16; i++) {
        float v = xs[w * XS_PITCH + i * 32 + lane];
        xsq += v * v;
    }
#pragma unroll
    for (int o = 16; o > 0; o >>= 1) xsq += __shfl_xor_sync(0xffffffffu, xsq, o);

    float delta = DELTA_C * sqrtf(xsq * candE);
    float ub = candV + delta;
#pragma unroll
    for (int o = 16; o > 0; o >>= 1) ub = fminf(ub, __shfl_xor_sync(0xffffffffu, ub, o));
    unsigned pm = __ballot_sync(0xffffffffu, candV - delta <= ub);

    float bestd = 3.4e38f;
    int bestc = SEM_SIZEV;
    while (pm) {
        int p = __ffs(pm) - 1;
        pm &= pm - 1;
        int c = __shfl_sync(0xffffffffu, candI, p);
        float eq = __shfl_sync(0xffffffffu, candE, p);
        const float* er = g_emb + (size_t)c * SEM_DIMV;
        float dot = 0.0f;
#pragma unroll
        for (int i = 0; i < 16; i++)
            dot += xs[w * XS_PITCH + i * 32 + lane] * er[i * 32 + lane];
#pragma unroll
        for (int o = 16; o > 0; o >>= 1) dot += __shfl_xor_sync(0xffffffffu, dot, o);
        float d2 = eq - 2.0f * dot;
        if (d2 < bestd || (d2 == bestd && c < bestc)) { bestd = d2; bestc = c; }
    }
    if (lane == 0) {
        codes_s[w] = bestc;
        outc[(size_t)b * 33 * TT + t0 + w] = (float)bestc;
    }
    __syncthreads();

    float psem = probs_sem[b];
    float* outqb = outq + (size_t)b * DTOT * TT + t0;
    if (psem < 0.5f) {
        int c = codes_s[w];
        const float* er = g_emb + (size_t)c * SEM_DIMV;
        __syncthreads();
#pragma unroll
        for (int i = 0; i < 16; i++)
            xs[w * XS_PITCH + i * 32 + lane] = er[i * 32 + lane];
        __syncthreads();
    }
#pragma unroll
    for (int it = 0; it < 16; it++) {
        int idx = it * 1024 + tid;
        int d = idx >> 5, t = idx & 31;
        outqb[(size_t)d * TT + t] = xs[t * XS_PITCH + d];
    }
}

// ---------------------------------------------------------------------------
__global__ void aco_kernel(const float* __restrict__ x,
                           const float* __restrict__ noise,
                           const float* __restrict__ probs_aco,
                           float* __restrict__ outq,
                           float* __restrict__ outc) {
    int idx = blockIdx.x * blockDim.x + threadIdx.x;
    int t = idx & 4095;
    int rj = idx >> 12;
    int b = rj >> 5, j = rj & 31;

    float a = x[((size_t)b * DTOT + SEM_DIMV + j) * TT + t];
    float zb = tanhf(a) * HALFV;
    float pa = probs_aco[b];
    float zout;
    if (pa < 0.5f) {
        zout = rintf(zb);
    } else if (pa < 0.75f) {
        float ns = (noise[(size_t)rj * TT + t] * 2.0f - 1.0f) * (HALFV / 9.0f);
        zout = fminf(fmaxf(zb + ns, -HALFV), HALFV);
    } else {
        zout = zb;
    }
    float code = fminf(fmaxf(rintf(zout + HALFV), 0.0f), 8.0f);
    outq[((size_t)b * DTOT + SEM_DIMV + j) * TT + t] = zout * 0.25f;
    outc[((size_t)b * 33 + 1 + j) * TT + t] = code;
}

// ---------------------------------------------------------------------------
extern "C" void kernel_launch(void* const* d_in, const int* in_sizes, int n_in,
                              void* d_out, int out_size) {
    const float* x     = (const float*)d_in[0];
    const float* esum  = (const float*)d_in[1];
    const float* usage = (const float*)d_in[2];
    const float* noise = (const float*)d_in[3];
    const float* psem  = (const float*)d_in[4];
    const float* paco  = (const float*)d_in[5];

    float* outq = (float*)d_out;
    float* outc = outq + (size_t)BB * DTOT * TT;

    cudaFuncSetAttribute(coarse_kernel,
                         cudaFuncAttributeMaxDynamicSharedMemorySize, DYN_BYTES);
    cudaFuncSetAttribute(rescore_kernel,
                         cudaFuncAttributeMaxDynamicSharedMemorySize, DYN_RESCORE);

    prep_emb_kernel<<<SEM_SIZEV, 128>>>(esum, usage);
    prep_B_kernel<<<64, 256>>>();
    prep_A_kernel<<<N_TILES * 8, 256>>>(x);
    coarse_kernel<<<N_TILES, 256, DYN_BYTES>>>();
    rescore_kernel<<<NROWS / 32, 1024, DYN_RESCORE>>>(x, psem, outq, outc);
    aco_kernel<<<(BB * ACO_DIMV * TT) / 256, 256>>>(x, noise, paco, outq, outc);
}

// round 7
// speedup vs baseline: 7.3741x; 1.0442x over previous
#include <cuda_runtime.h>
#include <cuda_bf16.h>
#include <cstdint>

#define SEM_DIMV 512
#define SEM_SIZEV 2048
#define ACO_DIMV 32
#define BB 16
#define TT 4096
#define NROWS (BB*TT)
#define DTOT 544
#define HALFV 4.0f
#define EPSV 1e-5f

#define TILE_M 64
#define N_TILES (NROWS/TILE_M)   // 1024
#define NC_COUNT 16              // 16 chunks of 128 codes
#define KK_COUNT 8
#define NSLOT 4
// slot: A hi 8KB @0, B hi 16KB @8192  -> 24KB
#define SLOT_BYTES 24576
#define ESQ_OFF (NSLOT*SLOT_BYTES)              // 98304
#define DYN_BYTES (ESQ_OFF + 8192 + 1024)       // ~105KB -> 2 CTAs/SM
#define DELTA_C 0.0088f

__device__ __align__(128) unsigned char g_A[N_TILES * 8 * 8192];   // 64MB
__device__ __align__(128) unsigned char g_B[128 * 16384];          // 2MB
__device__ float g_emb[SEM_SIZEV * SEM_DIMV];
__device__ float g_esq[SEM_SIZEV];
__device__ float g_candV[(size_t)NROWS * 32];                      // 8MB
__device__ int   g_candI[(size_t)NROWS * 32];                      // 8MB

// ------------------------------------------------------------------ helpers
__device__ __forceinline__ uint32_t smem_u32(const void* p) {
    uint32_t a;
    asm("{ .reg .u64 t; cvta.to.shared.u64 t, %1; cvt.u32.u64 %0, t; }" : "=r"(a) : "l"(p));
    return a;
}
__device__ __forceinline__ void mbar_init(uint32_t a, uint32_t cnt) {
    asm volatile("mbarrier.init.shared.b64 [%0], %1;" :: "r"(a), "r"(cnt) : "memory");
}
__device__ __forceinline__ void mbar_expect_tx(uint32_t a, uint32_t bytes) {
    asm volatile("mbarrier.arrive.expect_tx.shared.b64 _, [%0], %1;" :: "r"(a), "r"(bytes) : "memory");
}
__device__ __forceinline__ void mbar_arrive(uint32_t a) {
    asm volatile("mbarrier.arrive.shared.b64 _, [%0];" :: "r"(a) : "memory");
}
__device__ __forceinline__ void mbar_wait(uint32_t a, uint32_t parity) {
    asm volatile(
        "{\n\t.reg .pred P;\n\t"
        "W_%=:\n\t"
        "mbarrier.try_wait.parity.acquire.cta.shared::cta.b64 P, [%0], %1, 0x989680;\n\t"
        "@!P bra W_%=;\n\t}"
        :: "r"(a), "r"(parity) : "memory");
}
__device__ __forceinline__ void bulk_g2s(uint32_t dst, const void* src, uint32_t bytes, uint32_t mbar) {
    asm volatile("cp.async.bulk.shared::cluster.global.mbarrier::complete_tx::bytes [%0], [%1], %2, [%3];"
        :: "r"(dst), "l"(src), "r"(bytes), "r"(mbar) : "memory");
}

#define LDSM4(R0,R1,R2,R3,ADDR) \
    asm volatile("ldmatrix.sync.aligned.m8n8.x4.shared.b16 {%0,%1,%2,%3}, [%4];" \
        : "=r"(R0), "=r"(R1), "=r"(R2), "=r"(R3) : "r"(ADDR))

#define MMA16816(D, A0,A1,A2,A3, B0,B1) \
    asm volatile("mma.sync.aligned.m16n8k16.row.col.f32.bf16.bf16.f32 " \
        "{%0,%1,%2,%3},{%4,%5,%6,%7},{%8,%9},{%0,%1,%2,%3};" \
        : "+f"((D)[0]), "+f"((D)[1]), "+f"((D)[2]), "+f"((D)[3]) \
        : "r"(A0), "r"(A1), "r"(A2), "r"(A3), "r"(B0), "r"(B1))

__device__ __forceinline__ uint32_t pack_hi(float f0, float f1) {
    __nv_bfloat16 h0 = __float2bfloat16(f0);
    __nv_bfloat16 h1 = __float2bfloat16(f1);
    return (uint32_t)__bfloat16_as_ushort(h0) | ((uint32_t)__bfloat16_as_ushort(h1) << 16);
}
__device__ __forceinline__ void top2_ins(float v, int i, float* V, int* I) {
    if (v < V[0]) { V[1] = V[0]; I[1] = I[0]; V[0] = v; I[0] = i; }
    else if (v < V[1]) { V[1] = v; I[1] = i; }
}

// ---------------------------------------------------------------------------
__global__ void prep_emb_kernel(const float* __restrict__ esum,
                                const float* __restrict__ usage) {
    int c = blockIdx.x, tid = threadIdx.x;
    float inv = 1.0f / fmaxf(usage[c], EPSV);
    float acc = 0.0f;
#pragma unroll
    for (int i = 0; i < 4; i++) {
        int d = tid + i * 128;
        float e = esum[c * SEM_DIMV + d] * inv;
        g_emb[c * SEM_DIMV + d] = e;
        acc += e * e;
    }
    __shared__ float red[128];
    red[tid] = acc;
    __syncthreads();
    if (tid < 64) red[tid] += red[tid + 64];
    __syncthreads();
    if (tid < 32) {
        float v = red[tid] + red[tid + 32];
#pragma unroll
        for (int o = 16; o > 0; o >>= 1) v += __shfl_down_sync(0xffffffffu, v, o);
        if (tid == 0) g_esq[c] = v;
    }
}

// ---------------------------------------------------------------------------
// prep_B: 128-code x 64-k tiles, swizzled
// ---------------------------------------------------------------------------
__global__ void prep_B_kernel() {
    int tb = blockIdx.x;                 // nc*8 + kk, 128 blocks
    int nc = tb >> 3, kk = tb & 7;
    size_t base = (size_t)tb * 16384;
    for (int q = threadIdx.x; q < 1024; q += 256) {
        int m = q >> 3, c = q & 7;       // code row (0..127), k-chunk (0..7)
        const float* row = g_emb + (size_t)(nc * 128 + m) * SEM_DIMV + kk * 64 + c * 8;
        uint32_t hp[4];
#pragma unroll
        for (int i = 0; i < 4; i++) hp[i] = pack_hi(row[2*i], row[2*i+1]);
        uint32_t off = (uint32_t)m * 128 + ((uint32_t)(c ^ (m & 7)) << 4);
        *(uint4*)(g_B + base + off) = make_uint4(hp[0], hp[1], hp[2], hp[3]);
    }
}

// ---------------------------------------------------------------------------
__global__ __launch_bounds__(256)
void prep_A_kernel(const float* __restrict__ x) {
    __shared__ float s[64 * 65];
    int tile = blockIdx.x >> 3, kk = blockIdx.x & 7;
    int b = tile >> 6, t0 = (tile & 63) * 64;
    int tid = threadIdx.x;
#pragma unroll
    for (int i = 0; i < 16; i++) {
        int idx = i * 256 + tid;
        int k = idx >> 6, m = idx & 63;
        s[k * 65 + m] = x[((size_t)(b * DTOT + kk * 64 + k)) * TT + t0 + m];
    }
    __syncthreads();
    size_t base = (size_t)blockIdx.x * 8192;
    for (int q = tid; q < 512; q += 256) {
        int m = q >> 3, c = q & 7;
        uint32_t hp[4];
#pragma unroll
        for (int i = 0; i < 4; i++)
            hp[i] = pack_hi(s[(c * 8 + 2*i) * 65 + m], s[(c * 8 + 2*i + 1) * 65 + m]);
        uint32_t off = (uint32_t)m * 128 + ((uint32_t)(c ^ (m & 7)) << 4);
        *(uint4*)(g_A + base + off) = make_uint4(hp[0], hp[1], hp[2], hp[3]);
    }
}

// ---------------------------------------------------------------------------
// coarse: 1-pass hi*hi GEMM, 4-deep pipeline, warp tile 32x32
// per-thread top-2 per thread-slot (16 slots x 2 = 32 cand/row)
// ---------------------------------------------------------------------------
__global__ __launch_bounds__(256, 2)
void coarse_kernel() {
    extern __shared__ unsigned char dynraw[];
    __shared__ __align__(8) unsigned long long bars[2 * NSLOT];

    uint32_t raw = smem_u32(dynraw);
    uint32_t abase = (raw + 1023u) & ~1023u;
    float* esq_s = (float*)(dynraw + (abase - raw) + ESQ_OFF);
    uint32_t barF[NSLOT], barE[NSLOT];
#pragma unroll
    for (int i = 0; i < NSLOT; i++) {
        barF[i] = smem_u32(&bars[i]);
        barE[i] = smem_u32(&bars[NSLOT + i]);
    }

    int tid = threadIdx.x;
    int lane = tid & 31;
    int wid = tid >> 5;
    int warpM = wid >> 2, warpN = wid & 3;     // 2(M) x 4(N), warp 32x32
    int tile = blockIdx.x;

    if (tid == 0) {
#pragma unroll
        for (int i = 0; i < NSLOT; i++) { mbar_init(barF[i], 1); mbar_init(barE[i], 8); }
    }
    for (int i = tid; i < SEM_SIZEV; i += 256) esq_s[i] = g_esq[i];
    __syncthreads();

    const unsigned char* srcA = g_A + (size_t)tile * (8 * 8192);

    if (tid == 0) {
#pragma unroll
        for (int s = 0; s < NSLOT; s++) {      // nc0, kk 0..3
            mbar_expect_tx(barF[s], SLOT_BYTES);
            bulk_g2s(abase + s * SLOT_BYTES, srcA + (size_t)s * 8192, 8192, barF[s]);
            bulk_g2s(abase + s * SLOT_BYTES + 8192, g_B + (size_t)s * 16384, 16384, barF[s]);
        }
    }

    // hoisted ldmatrix geometry
    uint32_t sw = lane & 7;
    uint32_t aRowOff = (uint32_t)(warpM * 32 + (lane & 15)) * 128;
    uint32_t aAdd = lane >> 4;
    uint32_t bRowOff = (uint32_t)(warpN * 32 + (lane & 7) + ((lane & 16) >> 1)) * 128;
    uint32_t bAdd = (lane >> 3) & 1;
    uint32_t caOff[4], cbOff[4];
#pragma unroll
    for (int j = 0; j < 4; j++) {
        caOff[j] = aRowOff + (uint32_t)(((2 * j + aAdd) ^ sw) << 4);
        cbOff[j] = 8192u + bRowOff + (uint32_t)(((2 * j + bAdd) ^ sw) << 4);
    }

    float tV[2][2][2];
    int   tI[2][2][2];
#pragma unroll
    for (int mi = 0; mi < 2; mi++)
#pragma unroll
        for (int h = 0; h < 2; h++) {
            tV[mi][h][0] = tV[mi][h][1] = 3.4e38f;
            tI[mi][h][0] = tI[mi][h][1] = 0;
        }

    for (int nc = 0; nc < NC_COUNT; nc++) {
        float acc[2][4][4];
#pragma unroll
        for (int mi = 0; mi < 2; mi++)
#pragma unroll
            for (int nf = 0; nf < 4; nf++)
#pragma unroll
                for (int e = 0; e < 4; e++) acc[mi][nf][e] = 0.0f;

#pragma unroll
        for (int kk = 0; kk < KK_COUNT; kk++) {
            int s = nc * 8 + kk;
            int slot = kk & 3;
            uint32_t p = (uint32_t)(((nc << 1) + (kk >> 2)) & 1);
            mbar_wait(barF[slot], p);
            uint32_t sb = abase + slot * SLOT_BYTES;

#pragma unroll
            for (int j = 0; j < 4; j++) {
                uint32_t ar[2][4], br[2][4];
#pragma unroll
                for (int mi = 0; mi < 2; mi++)
                    LDSM4(ar[mi][0], ar[mi][1], ar[mi][2], ar[mi][3],
                          sb + caOff[j] + mi * 2048);
#pragma unroll
                for (int nf2 = 0; nf2 < 2; nf2++)
                    LDSM4(br[nf2][0], br[nf2][1], br[nf2][2], br[nf2][3],
                          sb + cbOff[j] + nf2 * 2048);
#pragma unroll
                for (int mi = 0; mi < 2; mi++)
#pragma unroll
                    for (int nf2 = 0; nf2 < 2; nf2++) {
                        MMA16816(acc[mi][2 * nf2],     ar[mi][0], ar[mi][1], ar[mi][2], ar[mi][3],
                                 br[nf2][0], br[nf2][1]);
                        MMA16816(acc[mi][2 * nf2 + 1], ar[mi][0], ar[mi][1], ar[mi][2], ar[mi][3],
                                 br[nf2][2], br[nf2][3]);
                    }
            }
            if (lane == 0) mbar_arrive(barE[slot]);

            if (tid == 0 && s + NSLOT < NC_COUNT * KK_COUNT) {
                mbar_wait(barE[slot], p);
                int s2 = s + NSLOT;
                int nc2 = s2 >> 3, kk2 = s2 & 7;
                mbar_expect_tx(barF[slot], SLOT_BYTES);
                bulk_g2s(sb, srcA + (size_t)kk2 * 8192, 8192, barF[slot]);
                bulk_g2s(sb + 8192, g_B + (size_t)(nc2 * 8 + kk2) * 16384, 16384, barF[slot]);
            }
        }

        // score this 128-code chunk
        int cbase = nc * 128 + warpN * 32 + (lane & 3) * 2;
#pragma unroll
        for (int nf = 0; nf < 4; nf++) {
            float eq0 = esq_s[cbase + nf * 8 + 0];
            float eq1 = esq_s[cbase + nf * 8 + 1];
            int c0 = cbase + nf * 8, c1 = c0 + 1;
#pragma unroll
            for (int mi = 0; mi < 2; mi++) {
                top2_ins(eq0 - 2.0f * acc[mi][nf][0], c0, tV[mi][0], tI[mi][0]);
                top2_ins(eq1 - 2.0f * acc[mi][nf][1], c1, tV[mi][0], tI[mi][0]);
                top2_ins(eq0 - 2.0f * acc[mi][nf][2], c0, tV[mi][1], tI[mi][1]);
                top2_ins(eq1 - 2.0f * acc[mi][nf][3], c1, tV[mi][1], tI[mi][1]);
            }
        }
    }

    // write 32 candidates per row
    int slotIdx = (warpN * 4 + (lane & 3)) * 2;
#pragma unroll
    for (int mi = 0; mi < 2; mi++)
#pragma unroll
        for (int h = 0; h < 2; h++) {
            int r = tile * 64 + warpM * 32 + mi * 16 + h * 8 + (lane >> 2);
            size_t base = (size_t)r * 32 + slotIdx;
            g_candV[base]     = tV[mi][h][0];
            g_candV[base + 1] = tV[mi][h][1];
            g_candI[base]     = tI[mi][h][0];
            g_candI[base + 1] = tI[mi][h][1];
        }
}

// ---------------------------------------------------------------------------
// rescore: warp per row; margin filter + exact fp32 rescore; sem output
// ---------------------------------------------------------------------------
#define XS_PITCH 513
#define DYN_RESCORE (32 * XS_PITCH * 4)

__global__ __launch_bounds__(1024)
void rescore_kernel(const float* __restrict__ x,
                    const float* __restrict__ probs_sem,
                    float* __restrict__ outq,
                    float* __restrict__ outc) {
    extern __shared__ float xs[];
    __shared__ int codes_s[32];

    int tid = threadIdx.x;
    int lane = tid & 31;
    int w = tid >> 5;
    int b = blockIdx.x >> 7;
    int t0 = (blockIdx.x & 127) * 32;

    const float* xb = x + (size_t)b * DTOT * TT + t0;

#pragma unroll
    for (int it = 0; it < 16; it++) {
        int idx = it * 1024 + tid;
        int d = idx >> 5, t = idx & 31;
        xs[t * XS_PITCH + d] = xb[(size_t)d * TT + t];
    }
    __syncthreads();

    int r = blockIdx.x * 32 + w;
    float candV = g_candV[(size_t)r * 32 + lane];
    int   candI = g_candI[(size_t)r * 32 + lane];
    float candE = g_esq[candI];

    float xsq = 0.0f;
#pragma unroll
    for (int i = 0; i < 16; i++) {
        float v = xs[w * XS_PITCH + i * 32 + lane];
        xsq += v * v;
    }
#pragma unroll
    for (int o = 16; o > 0; o >>= 1) xsq += __shfl_xor_sync(0xffffffffu, xsq, o);

    float delta = DELTA_C * sqrtf(xsq * candE);
    float ub = candV + delta;
#pragma unroll
    for (int o = 16; o > 0; o >>= 1) ub = fminf(ub, __shfl_xor_sync(0xffffffffu, ub, o));
    unsigned pm = __ballot_sync(0xffffffffu, candV - delta <= ub);

    float bestd = 3.4e38f;
    int bestc = SEM_SIZEV;
    while (pm) {
        int p = __ffs(pm) - 1;
        pm &= pm - 1;
        int c = __shfl_sync(0xffffffffu, candI, p);
        float eq = __shfl_sync(0xffffffffu, candE, p);
        const float* er = g_emb + (size_t)c * SEM_DIMV;
        float dot = 0.0f;
#pragma unroll
        for (int i = 0; i < 16; i++)
            dot += xs[w * XS_PITCH + i * 32 + lane] * er[i * 32 + lane];
#pragma unroll
        for (int o = 16; o > 0; o >>= 1) dot += __shfl_xor_sync(0xffffffffu, dot, o);
        float d2 = eq - 2.0f * dot;
        if (d2 < bestd || (d2 == bestd && c < bestc)) { bestd = d2; bestc = c; }
    }
    if (lane == 0) {
        codes_s[w] = bestc;
        outc[(size_t)b * 33 * TT + t0 + w] = (float)bestc;
    }
    __syncthreads();

    float psem = probs_sem[b];
    float* outqb = outq + (size_t)b * DTOT * TT + t0;
    if (psem < 0.5f) {
        int c = codes_s[w];
        const float* er = g_emb + (size_t)c * SEM_DIMV;
        __syncthreads();
#pragma unroll
        for (int i = 0; i < 16; i++)
            xs[w * XS_PITCH + i * 32 + lane] = er[i * 32 + lane];
        __syncthreads();
    }
#pragma unroll
    for (int it = 0; it < 16; it++) {
        int idx = it * 1024 + tid;
        int d = idx >> 5, t = idx & 31;
        outqb[(size_t)d * TT + t] = xs[t * XS_PITCH + d];
    }
}

// ---------------------------------------------------------------------------
__global__ void aco_kernel(const float* __restrict__ x,
                           const float* __restrict__ noise,
                           const float* __restrict__ probs_aco,
                           float* __restrict__ outq,
                           float* __restrict__ outc) {
    int idx = blockIdx.x * blockDim.x + threadIdx.x;
    int t = idx & 4095;
    int rj = idx >> 12;
    int b = rj >> 5, j = rj & 31;

    float a = x[((size_t)b * DTOT + SEM_DIMV + j) * TT + t];
    float zb = tanhf(a) * HALFV;
    float pa = probs_aco[b];
    float zout;
    if (pa < 0.5f) {
        zout = rintf(zb);
    } else if (pa < 0.75f) {
        float ns = (noise[(size_t)rj * TT + t] * 2.0f - 1.0f) * (HALFV / 9.0f);
        zout = fminf(fmaxf(zb + ns, -HALFV), HALFV);
    } else {
        zout = zb;
    }
    float code = fminf(fmaxf(rintf(zout + HALFV), 0.0f), 8.0f);
    outq[((size_t)b * DTOT + SEM_DIMV + j) * TT + t] = zout * 0.25f;
    outc[((size_t)b * 33 + 1 + j) * TT + t] = code;
}

// ---------------------------------------------------------------------------
extern "C" void kernel_launch(void* const* d_in, const int* in_sizes, int n_in,
                              void* d_out, int out_size) {
    const float* x     = (const float*)d_in[0];
    const float* esum  = (const float*)d_in[1];
    const float* usage = (const float*)d_in[2];
    const float* noise = (const float*)d_in[3];
    const float* psem  = (const float*)d_in[4];
    const float* paco  = (const float*)d_in[5];

    float* outq = (float*)d_out;
    float* outc = outq + (size_t)BB * DTOT * TT;

    cudaFuncSetAttribute(coarse_kernel,
                         cudaFuncAttributeMaxDynamicSharedMemorySize, DYN_BYTES);
    cudaFuncSetAttribute(rescore_kernel,
                         cudaFuncAttributeMaxDynamicSharedMemorySize, DYN_RESCORE);

    prep_emb_kernel<<<SEM_SIZEV, 128>>>(esum, usage);
    prep_B_kernel<<<128, 256>>>();
    prep_A_kernel<<<N_TILES * 8, 256>>>(x);
    coarse_kernel<<<N_TILES, 256, DYN_BYTES>>>();
    rescore_kernel<<<NROWS / 32, 1024, DYN_RESCORE>>>(x, psem, outq, outc);
    aco_kernel<<<(BB * ACO_DIMV * TT) / 256, 256>>>(x, noise, paco, outq, outc);
}